// round 2
// baseline (speedup 1.0000x reference)
#include <cuda_runtime.h>
#include <cstdint>

#define N_PTS 131072
#define D_IN  512
#define D_H   128
#define KC    256

typedef unsigned long long ull;

// ---------------- scratch (device globals; no allocation allowed) ----------
__device__ float  g_latentT[D_H * N_PTS];    // [d][m], 64 MB
__device__ float  g_restoredT[D_H * N_PTS];  // [d][m], 64 MB
__device__ float  g_cbnorm[3 * KC];
__device__ int    g_used[3 * KC];
__device__ double g_remsq;
__device__ double g_reconsq;

extern __shared__ char smem_raw[];

// ---------------- f32x2 helpers (Blackwell packed dual-fp32 FMA) -----------
__device__ __forceinline__ ull pack2(float lo, float hi) {
    ull r;
    asm("mov.b64 %0, {%1, %2};" : "=l"(r)
        : "r"(__float_as_uint(lo)), "r"(__float_as_uint(hi)));
    return r;
}
__device__ __forceinline__ void unpack2(ull v, float& lo, float& hi) {
    unsigned a, b;
    asm("mov.b64 {%0, %1}, %2;" : "=r"(a), "=r"(b) : "l"(v));
    lo = __uint_as_float(a); hi = __uint_as_float(b);
}
__device__ __forceinline__ ull fma2(ull a, ull b, ull c) {
    ull d;
    asm("fma.rn.f32x2 %0, %1, %2, %3;" : "=l"(d) : "l"(a), "l"(b), "l"(c));
    return d;
}
__device__ __forceinline__ float warp_sum(float v) {
    #pragma unroll
    for (int o = 16; o; o >>= 1) v += __shfl_xor_sync(0xffffffffu, v, o);
    return v;
}

// ---------------- K0: init + codebook norms --------------------------------
__global__ void k_init(const float* __restrict__ cb0,
                       const float* __restrict__ cb1,
                       const float* __restrict__ cb2) {
    int i = blockIdx.x * 256 + threadIdx.x;
    if (i == 0) { g_remsq = 0.0; g_reconsq = 0.0; }
    if (i < 3 * KC) {
        g_used[i] = 0;
        const float* cb = (i < KC) ? cb0 : (i < 2 * KC ? cb1 : cb2);
        int c = i & (KC - 1);
        float s = 0.f;
        #pragma unroll 8
        for (int d = 0; d < D_H; d++) { float v = cb[c * D_H + d]; s = fmaf(v, v, s); }
        g_cbnorm[i] = s;
    }
}

// ---------------- K1: latentT = (emb @ W_enc^T)^T --------------------------
// thread-per-point; W_enc half (64 cols) transposed in smem, emb tile staged
// transposed. Dominated by 32 FFMA2 per k per thread (FMA-pipe-bound).
struct SmemLat {
    ull   WT2[512][34];     // [k][n-pair] for current half (pad 34: 16B-aligned rows)
    float embST[64][258];   // [k-chunk][point]
};

__global__ void __launch_bounds__(256, 1)
k_latent(const float* __restrict__ emb, const float* __restrict__ W_enc) {
    SmemLat& S = *reinterpret_cast<SmemLat*>(smem_raw);
    const int tid = threadIdx.x;
    const int m0  = blockIdx.x * 256;
    const int m   = m0 + tid;

    for (int h = 0; h < 2; h++) {
        __syncthreads();  // previous-half readers done
        // build transposed W_enc half: WT2[k][j] = {W[h*64+2j][k], W[h*64+2j+1][k]}
        for (int idx = tid; idx < 512 * 32; idx += 256) {
            int k = idx & 511, j = idx >> 9;
            int n = h * 64 + 2 * j;
            S.WT2[k][j] = pack2(W_enc[n * 512 + k], W_enc[(n + 1) * 512 + k]);
        }
        ull acc[32];
        #pragma unroll
        for (int j = 0; j < 32; j++) acc[j] = 0ull;

        for (int kc = 0; kc < 8; kc++) {
            __syncthreads();
            for (int idx = tid; idx < 64 * 256; idx += 256) {
                int kk = idx & 63, p = idx >> 6;
                S.embST[kk][p] = emb[(m0 + p) * 512 + kc * 64 + kk];
            }
            __syncthreads();
            #pragma unroll 4
            for (int kk = 0; kk < 64; kk++) {
                float v = S.embST[kk][tid];
                ull v2 = pack2(v, v);
                const ulonglong2* w =
                    reinterpret_cast<const ulonglong2*>(&S.WT2[kc * 64 + kk][0]);
                #pragma unroll
                for (int j2 = 0; j2 < 16; j2++) {
                    ulonglong2 ww = w[j2];
                    acc[2 * j2]     = fma2(v2, ww.x, acc[2 * j2]);
                    acc[2 * j2 + 1] = fma2(v2, ww.y, acc[2 * j2 + 1]);
                }
            }
        }
        #pragma unroll
        for (int j = 0; j < 32; j++) {
            float lo, hi; unpack2(acc[j], lo, hi);
            int n = h * 64 + 2 * j;
            g_latentT[n * N_PTS + m]       = lo;   // coalesced over m
            g_latentT[(n + 1) * N_PTS + m] = hi;
        }
    }
}

// ---------------- K2: fused 3-stage RQ (argmin + update + loss) ------------
// thread-per-point, remainder in 128 registers across all 3 stages.
struct SmemStg {
    ull   cb2[KC * 64];  // 128 KB: codebook as f32 pairs
    float cbn[KC];
};

__global__ void __launch_bounds__(256, 1)
k_stages(const float* __restrict__ cb0, const float* __restrict__ cb1,
         const float* __restrict__ cb2g) {
    SmemStg& S = *reinterpret_cast<SmemStg*>(smem_raw);
    const int tid = threadIdx.x;
    const int m   = blockIdx.x * 256 + tid;

    ull rem[64];
    #pragma unroll
    for (int i = 0; i < 64; i++)
        rem[i] = pack2(g_latentT[(2 * i) * N_PTS + m],
                       g_latentT[(2 * i + 1) * N_PTS + m]);

    float sq = 0.f;
    for (int s = 0; s < 3; s++) {
        const float* cb = (s == 0) ? cb0 : (s == 1 ? cb1 : cb2g);
        __syncthreads();  // previous-stage smem readers done
        {
            const float4* src = reinterpret_cast<const float4*>(cb);
            float4* dst = reinterpret_cast<float4*>(S.cb2);
            for (int idx = tid; idx < KC * D_H / 4; idx += 256) dst[idx] = src[idx];
            if (tid < KC) S.cbn[tid] = g_cbnorm[s * KC + tid];
        }
        __syncthreads();

        float best = 3.4e38f; int bi = 0;
        for (int c = 0; c < KC; c += 2) {
            ull a0 = 0, a1 = 0, b0 = 0, b1 = 0;
            const ulonglong2* p0 =
                reinterpret_cast<const ulonglong2*>(S.cb2 + (size_t)c * 64);
            const ulonglong2* p1 =
                reinterpret_cast<const ulonglong2*>(S.cb2 + (size_t)(c + 1) * 64);
            #pragma unroll
            for (int i = 0; i < 32; i++) {          // uniform-addr broadcast LDS
                ulonglong2 x = p0[i], y = p1[i];
                a0 = fma2(rem[2 * i],     x.x, a0);
                a1 = fma2(rem[2 * i + 1], x.y, a1);
                b0 = fma2(rem[2 * i],     y.x, b0);
                b1 = fma2(rem[2 * i + 1], y.y, b1);
            }
            float ax, ay, bx, by;
            unpack2(a0, ax, ay); unpack2(a1, bx, by);
            float dot0 = (ax + ay) + (bx + by);
            unpack2(b0, ax, ay); unpack2(b1, bx, by);
            float dot1 = (ax + ay) + (bx + by);
            float s0 = S.cbn[c]     - 2.f * dot0;   // argmin of ||r-c||^2
            float s1 = S.cbn[c + 1] - 2.f * dot1;
            if (s0 < best) { best = s0; bi = c; }       // first-index tie-break
            if (s1 < best) { best = s1; bi = c + 1; }
        }
        g_used[s * KC + bi] = 1;

        const ull* crow = S.cb2 + (size_t)bi * 64;
        #pragma unroll
        for (int i = 0; i < 64; i++) {
            float rl, rh, cl, ch;
            unpack2(rem[i], rl, rh);
            unpack2(crow[i], cl, ch);
            rl -= cl; rh -= ch;
            sq = fmaf(rl, rl, sq); sq = fmaf(rh, rh, sq);
            rem[i] = pack2(rl, rh);
        }
    }
    // restored = latent - rem_final  (coalesced over m)
    #pragma unroll
    for (int i = 0; i < 64; i++) {
        float rl, rh; unpack2(rem[i], rl, rh);
        g_restoredT[(2 * i) * N_PTS + m]     = g_latentT[(2 * i) * N_PTS + m] - rl;
        g_restoredT[(2 * i + 1) * N_PTS + m] = g_latentT[(2 * i + 1) * N_PTS + m] - rh;
    }
    float tot = warp_sum(sq);
    if ((tid & 31) == 0) atomicAdd(&g_remsq, (double)tot);
}

// ---------------- K3: recon MSE via fused GEMM2 ----------------------------
// C[m][n] = sum_k restored[m][k] * W_dec[n][k]; accumulate (C - emb)^2.
__global__ void __launch_bounds__(256)
k_decode(const float* __restrict__ emb, const float* __restrict__ W_dec) {
    __shared__ __align__(16) float As[16][128];
    __shared__ __align__(16) ull   Bs2[16][66];
    const int tid = threadIdx.x;
    const int tx = tid & 15, ty = tid >> 4;
    const int m0 = blockIdx.y * 128, n0 = blockIdx.x * 128;

    ull acc[8][4];
    #pragma unroll
    for (int i = 0; i < 8; i++)
        #pragma unroll
        for (int j = 0; j < 4; j++) acc[i][j] = 0ull;

    for (int kc = 0; kc < 8; kc++) {
        const int k0 = kc * 16;
        __syncthreads();
        for (int idx = tid; idx < 2048; idx += 256) {       // restoredT is K-major
            int kk = idx >> 7, mm = idx & 127;
            As[kk][mm] = g_restoredT[(k0 + kk) * N_PTS + m0 + mm];
        }
        for (int idx = tid; idx < 1024; idx += 256) {
            int kk = idx & 15, j = idx >> 4;
            int n = n0 + 2 * j;
            Bs2[kk][j] = pack2(W_dec[n * 128 + k0 + kk],
                               W_dec[(n + 1) * 128 + k0 + kk]);
        }
        __syncthreads();
        #pragma unroll
        for (int kk = 0; kk < 16; kk++) {
            float4 aA = *reinterpret_cast<const float4*>(&As[kk][ty * 8]);
            float4 aB = *reinterpret_cast<const float4*>(&As[kk][ty * 8 + 4]);
            ull ad[8];
            ad[0] = pack2(aA.x, aA.x); ad[1] = pack2(aA.y, aA.y);
            ad[2] = pack2(aA.z, aA.z); ad[3] = pack2(aA.w, aA.w);
            ad[4] = pack2(aB.x, aB.x); ad[5] = pack2(aB.y, aB.y);
            ad[6] = pack2(aB.z, aB.z); ad[7] = pack2(aB.w, aB.w);
            const ulonglong2* bp = reinterpret_cast<const ulonglong2*>(&Bs2[kk][0]);
            ulonglong2 bA = bp[tx * 2], bB = bp[tx * 2 + 1];
            ull bv[4] = { bA.x, bA.y, bB.x, bB.y };
            #pragma unroll
            for (int i = 0; i < 8; i++)
                #pragma unroll
                for (int j2 = 0; j2 < 4; j2++)
                    acc[i][j2] = fma2(ad[i], bv[j2], acc[i][j2]);
        }
    }
    // fused MSE epilogue; emb read coalesced (n contiguous over tx)
    float sq = 0.f;
    #pragma unroll
    for (int i = 0; i < 8; i++) {
        const float4* e = reinterpret_cast<const float4*>(
            &emb[(size_t)(m0 + ty * 8 + i) * 512 + n0 + tx * 8]);
        float4 e0 = e[0], e1 = e[1];
        float c0, c1;
        unpack2(acc[i][0], c0, c1);
        { float d0 = c0 - e0.x, d1 = c1 - e0.y; sq = fmaf(d0, d0, sq); sq = fmaf(d1, d1, sq); }
        unpack2(acc[i][1], c0, c1);
        { float d0 = c0 - e0.z, d1 = c1 - e0.w; sq = fmaf(d0, d0, sq); sq = fmaf(d1, d1, sq); }
        unpack2(acc[i][2], c0, c1);
        { float d0 = c0 - e1.x, d1 = c1 - e1.y; sq = fmaf(d0, d0, sq); sq = fmaf(d1, d1, sq); }
        unpack2(acc[i][3], c0, c1);
        { float d0 = c0 - e1.z, d1 = c1 - e1.w; sq = fmaf(d0, d0, sq); sq = fmaf(d1, d1, sq); }
    }
    float tot = warp_sum(sq);
    if ((tid & 31) == 0) atomicAdd(&g_reconsq, (double)tot);
}

// ---------------- K4: finalize ---------------------------------------------
__global__ void k_final(float* __restrict__ out, int out_size) {
    __shared__ float vals[6];
    int tid = threadIdx.x;
    if (tid == 0) {
        double recon = g_reconsq / ((double)N_PTS * (double)D_IN);
        double rq    = 1.25 * g_remsq / ((double)N_PTS * (double)D_H);
        vals[0] = (float)(recon + rq);
        vals[1] = (float)recon;
        vals[2] = (float)rq;
    }
    if (tid < 3) {
        int cnt = 0;
        for (int c = 0; c < KC; c++) cnt += g_used[tid * KC + c];
        vals[3 + tid] = (float)cnt;
    }
    __syncthreads();
    if (tid < 6 && tid < out_size) out[tid] = vals[tid];
}

// ---------------- launch ----------------------------------------------------
extern "C" void kernel_launch(void* const* d_in, const int* in_sizes, int n_in,
                              void* d_out, int out_size) {
    const float* emb   = (const float*)d_in[0];
    const float* W_enc = (const float*)d_in[1];
    const float* W_dec = (const float*)d_in[2];
    const float* cb0   = (const float*)d_in[3];
    const float* cb1   = (const float*)d_in[4];
    const float* cb2   = (const float*)d_in[5];
    float* out = (float*)d_out;

    cudaFuncSetAttribute(k_latent, cudaFuncAttributeMaxDynamicSharedMemorySize,
                         (int)sizeof(SmemLat));
    cudaFuncSetAttribute(k_stages, cudaFuncAttributeMaxDynamicSharedMemorySize,
                         (int)sizeof(SmemStg));

    k_init<<<3, 256>>>(cb0, cb1, cb2);
    k_latent<<<N_PTS / 256, 256, sizeof(SmemLat)>>>(emb, W_enc);
    k_stages<<<N_PTS / 256, 256, sizeof(SmemStg)>>>(cb0, cb1, cb2);
    k_decode<<<dim3(4, N_PTS / 128), 256>>>(emb, W_dec);
    k_final<<<1, 32>>>(out, out_size);
}

// round 10
// speedup vs baseline: 1.6201x; 1.6201x over previous
#include <cuda_runtime.h>
#include <cuda_bf16.h>
#include <cstdint>

#define N_PTS 131072
#define D_IN  512
#define D_H   128
#define KC    256

typedef unsigned long long ull;

// ---------------- scratch (device globals; no allocation allowed) ----------
__device__ float  g_latentT[D_H * N_PTS];    // [d][m]
__device__ float  g_restoredT[D_H * N_PTS];  // [d][m]
__device__ float  g_cbnorm[3 * KC];
__device__ int    g_used[3 * KC];
__device__ double g_remsq;
__device__ double g_reconsq;

extern __shared__ char smem_raw[];

#define SMEM_SWIZZLE_128B(bo) ((bo) ^ (((bo) >> 3) & 0x70))

// ---------------- generic helpers ------------------------------------------
__device__ __forceinline__ uint32_t smem_to_u32(const void* p) {
    uint32_t a;
    asm("{ .reg .u64 t; cvta.to.shared.u64 t, %1; cvt.u32.u64 %0, t; }"
        : "=r"(a) : "l"(p));
    return a;
}
__device__ __forceinline__ ull pack2(float lo, float hi) {
    ull r;
    asm("mov.b64 %0, {%1, %2};" : "=l"(r)
        : "r"(__float_as_uint(lo)), "r"(__float_as_uint(hi)));
    return r;
}
__device__ __forceinline__ void unpack2(ull v, float& lo, float& hi) {
    unsigned a, b;
    asm("mov.b64 {%0, %1}, %2;" : "=r"(a), "=r"(b) : "l"(v));
    lo = __uint_as_float(a); hi = __uint_as_float(b);
}
__device__ __forceinline__ ull fma2(ull a, ull b, ull c) {
    ull d;
    asm("fma.rn.f32x2 %0, %1, %2, %3;" : "=l"(d) : "l"(a), "l"(b), "l"(c));
    return d;
}
__device__ __forceinline__ float warp_sum(float v) {
    #pragma unroll
    for (int o = 16; o; o >>= 1) v += __shfl_xor_sync(0xffffffffu, v, o);
    return v;
}

// ---------------- mma.sync helpers (family-safe HMMA path) ------------------
__device__ __forceinline__ void ldmx4(uint32_t* r, uint32_t addr) {
    asm volatile("ldmatrix.sync.aligned.m8n8.x4.shared.b16 {%0,%1,%2,%3}, [%4];"
        : "=r"(r[0]), "=r"(r[1]), "=r"(r[2]), "=r"(r[3]) : "r"(addr));
}
__device__ __forceinline__ void mma16816(float* c, const uint32_t* a, const uint32_t* b) {
    asm volatile(
        "mma.sync.aligned.m16n8k16.row.col.f32.bf16.bf16.f32 "
        "{%0,%1,%2,%3}, {%4,%5,%6,%7}, {%8,%9}, {%0,%1,%2,%3};"
        : "+f"(c[0]), "+f"(c[1]), "+f"(c[2]), "+f"(c[3])
        : "r"(a[0]), "r"(a[1]), "r"(a[2]), "r"(a[3]), "r"(b[0]), "r"(b[1]));
}

// Convert one float4 (4 consecutive k of one row) into bf16 hi/lo tiles.
// Tile rows are 128 bytes (64 bf16), XOR-swizzled.
__device__ __forceinline__ void sts_split4(float4 v, int r, int kk, char* dh, char* dl) {
    uint32_t off = SMEM_SWIZZLE_128B((uint32_t)(r * 128 + kk * 2));
    __nv_bfloat162 h01 = __float22bfloat162_rn(make_float2(v.x, v.y));
    __nv_bfloat162 h23 = __float22bfloat162_rn(make_float2(v.z, v.w));
    float2 f01 = __bfloat1622float2(h01);
    float2 f23 = __bfloat1622float2(h23);
    __nv_bfloat162 l01 = __float22bfloat162_rn(make_float2(v.x - f01.x, v.y - f01.y));
    __nv_bfloat162 l23 = __float22bfloat162_rn(make_float2(v.z - f23.x, v.w - f23.y));
    uint2 hh, ll;
    hh.x = *reinterpret_cast<uint32_t*>(&h01);
    hh.y = *reinterpret_cast<uint32_t*>(&h23);
    ll.x = *reinterpret_cast<uint32_t*>(&l01);
    ll.y = *reinterpret_cast<uint32_t*>(&l23);
    *reinterpret_cast<uint2*>(dh + off) = hh;
    *reinterpret_cast<uint2*>(dl + off) = ll;
}

// Stage A[m][k] 128x64 from K-major source srcT[k][m] into bf16 hi/lo tiles.
__device__ __forceinline__ void stage_colmajor_split(
    const float* __restrict__ srcT, int m0, int k0,
    char* dh, char* dl, int tid)
{
    int kr = tid & 63, mq = tid >> 6;
    const float4* p = reinterpret_cast<const float4*>(
        srcT + (size_t)(k0 + kr) * N_PTS + m0 + mq * 32);
    #pragma unroll
    for (int q = 0; q < 8; q++) {
        float4 v = p[q];
        int mb = mq * 32 + q * 4;
        float vv[4] = {v.x, v.y, v.z, v.w};
        #pragma unroll
        for (int e = 0; e < 4; e++) {
            float a = vv[e];
            __nv_bfloat16 h = __float2bfloat16(a);
            __nv_bfloat16 l = __float2bfloat16(a - __bfloat162float(h));
            uint32_t off = SMEM_SWIZZLE_128B((uint32_t)((mb + e) * 128 + kr * 2));
            *reinterpret_cast<__nv_bfloat16*>(dh + off) = h;
            *reinterpret_cast<__nv_bfloat16*>(dl + off) = l;
        }
    }
}

// One K=64 chunk, 3 split combos (AhBh, AlBh, AhBl) x 4 ksteps of K=16.
// Block tile 128m x 128n, 8 warps as 4(m) x 2(n); warp tile 32m x 64n.
__device__ __forceinline__ void mma_chunk(
    float acc[2][8][4], char* Ah, char* Al, char* Bh, char* Bl,
    int wm, int wn, int lane)
{
    uint32_t aT[3] = { smem_to_u32(Ah), smem_to_u32(Al), smem_to_u32(Ah) };
    uint32_t bT[3] = { smem_to_u32(Bh), smem_to_u32(Bh), smem_to_u32(Bl) };
    const int g = lane >> 3, rr = lane & 7;
    const int a_row = (g & 1) * 8 + rr, a_col = (g >> 1) * 8;  // within 16x16
    const int b_row = (g >> 1) * 8 + rr, b_col = (g & 1) * 8;  // (n, k) within 16x16
    #pragma unroll
    for (int c = 0; c < 3; c++) {
        #pragma unroll
        for (int ks = 0; ks < 4; ks++) {
            const int k0 = ks * 16;
            uint32_t a[2][4], b[4][4];
            #pragma unroll
            for (int mt = 0; mt < 2; mt++) {
                int row = wm + mt * 16 + a_row;
                ldmx4(a[mt], aT[c] +
                      SMEM_SWIZZLE_128B((uint32_t)(row * 128 + (k0 + a_col) * 2)));
            }
            #pragma unroll
            for (int np = 0; np < 4; np++) {
                int n = wn + np * 16 + b_row;
                ldmx4(b[np], bT[c] +
                      SMEM_SWIZZLE_128B((uint32_t)(n * 128 + (k0 + b_col) * 2)));
            }
            #pragma unroll
            for (int mt = 0; mt < 2; mt++)
                #pragma unroll
                for (int nt = 0; nt < 8; nt++)
                    mma16816(acc[mt][nt], a[mt], &b[nt >> 1][(nt & 1) * 2]);
        }
    }
}

// ---------------- K0: init + codebook norms --------------------------------
__global__ void k_init(const float* __restrict__ cb0,
                       const float* __restrict__ cb1,
                       const float* __restrict__ cb2) {
    int i = blockIdx.x * 256 + threadIdx.x;
    if (i == 0) { g_remsq = 0.0; g_reconsq = 0.0; }
    if (i < 3 * KC) {
        g_used[i] = 0;
        const float* cb = (i < KC) ? cb0 : (i < 2 * KC ? cb1 : cb2);
        int c = i & (KC - 1);
        float s = 0.f;
        #pragma unroll 8
        for (int d = 0; d < D_H; d++) { float v = cb[c * D_H + d]; s = fmaf(v, v, s); }
        g_cbnorm[i] = s;
    }
}

// ---------------- GEMM1 (HMMA bf16x3): latentT = (emb @ W_enc^T)^T ---------
__global__ void __launch_bounds__(256, 1)
k_gemm1(const float* __restrict__ emb, const float* __restrict__ W_enc) {
    char* Ah = smem_raw;
    char* Al = smem_raw + 16384;
    char* Bh = smem_raw + 32768;
    char* Bl = smem_raw + 49152;
    const int tid = threadIdx.x, lane = tid & 31, wid = tid >> 5;
    const int m0 = blockIdx.x * 128;
    const int wm = (wid >> 1) * 32, wn = (wid & 1) * 64;
    const int r = tid >> 1, half = tid & 1;

    float acc[2][8][4];
    #pragma unroll
    for (int i = 0; i < 2; i++)
        #pragma unroll
        for (int j = 0; j < 8; j++)
            #pragma unroll
            for (int k = 0; k < 4; k++) acc[i][j][k] = 0.f;

    const float* aRow = emb + (size_t)(m0 + r) * 512 + half * 32;
    const float* bRow = W_enc + (size_t)r * 512 + half * 32;

    float4 pa[8];
    #pragma unroll
    for (int q = 0; q < 8; q++) pa[q] = reinterpret_cast<const float4*>(aRow)[q];

    for (int ch = 0; ch < 8; ch++) {
        #pragma unroll
        for (int q = 0; q < 8; q++) {
            sts_split4(pa[q], r, half * 32 + q * 4, Ah, Al);
            float4 vb = reinterpret_cast<const float4*>(bRow + ch * 64)[q];
            sts_split4(vb, r, half * 32 + q * 4, Bh, Bl);
        }
        __syncthreads();
        if (ch < 7) {
            #pragma unroll
            for (int q = 0; q < 8; q++)
                pa[q] = reinterpret_cast<const float4*>(aRow + (ch + 1) * 64)[q];
        }
        mma_chunk(acc, Ah, Al, Bh, Bl, wm, wn, lane);
        __syncthreads();
    }

    // epilogue: write latentT[n][m] (8 consecutive m per lane-group = 32B sectors)
    #pragma unroll
    for (int mt = 0; mt < 2; mt++) {
        int m = m0 + wm + mt * 16 + (lane >> 2);
        #pragma unroll
        for (int nt = 0; nt < 8; nt++) {
            int n = wn + nt * 8 + (lane & 3) * 2;
            g_latentT[(size_t)n * N_PTS + m]           = acc[mt][nt][0];
            g_latentT[(size_t)(n + 1) * N_PTS + m]     = acc[mt][nt][1];
            g_latentT[(size_t)n * N_PTS + m + 8]       = acc[mt][nt][2];
            g_latentT[(size_t)(n + 1) * N_PTS + m + 8] = acc[mt][nt][3];
        }
    }
}

// ---------------- K2: fused 3-stage RQ (unchanged, passed R2) --------------
struct SmemStg {
    ull   cb2[KC * 64];
    float cbn[KC];
};

__global__ void __launch_bounds__(256, 1)
k_stages(const float* __restrict__ cb0, const float* __restrict__ cb1,
         const float* __restrict__ cb2g) {
    SmemStg& S = *reinterpret_cast<SmemStg*>(smem_raw);
    const int tid = threadIdx.x;
    const int m   = blockIdx.x * 256 + tid;

    ull rem[64];
    #pragma unroll
    for (int i = 0; i < 64; i++)
        rem[i] = pack2(g_latentT[(2 * i) * (size_t)N_PTS + m],
                       g_latentT[(2 * i + 1) * (size_t)N_PTS + m]);

    float sq = 0.f;
    for (int s = 0; s < 3; s++) {
        const float* cb = (s == 0) ? cb0 : (s == 1 ? cb1 : cb2g);
        __syncthreads();
        {
            const float4* src = reinterpret_cast<const float4*>(cb);
            float4* dst = reinterpret_cast<float4*>(S.cb2);
            for (int idx = tid; idx < KC * D_H / 4; idx += 256) dst[idx] = src[idx];
            if (tid < KC) S.cbn[tid] = g_cbnorm[s * KC + tid];
        }
        __syncthreads();

        float best = 3.4e38f; int bi = 0;
        for (int c = 0; c < KC; c += 2) {
            ull a0 = 0, a1 = 0, b0 = 0, b1 = 0;
            const ulonglong2* p0 = reinterpret_cast<const ulonglong2*>(S.cb2 + (size_t)c * 64);
            const ulonglong2* p1 = reinterpret_cast<const ulonglong2*>(S.cb2 + (size_t)(c + 1) * 64);
            #pragma unroll
            for (int i = 0; i < 32; i++) {
                ulonglong2 x = p0[i], y = p1[i];
                a0 = fma2(rem[2 * i],     x.x, a0);
                a1 = fma2(rem[2 * i + 1], x.y, a1);
                b0 = fma2(rem[2 * i],     y.x, b0);
                b1 = fma2(rem[2 * i + 1], y.y, b1);
            }
            float ax, ay, bx, by;
            unpack2(a0, ax, ay); unpack2(a1, bx, by);
            float dot0 = (ax + ay) + (bx + by);
            unpack2(b0, ax, ay); unpack2(b1, bx, by);
            float dot1 = (ax + ay) + (bx + by);
            float s0 = S.cbn[c]     - 2.f * dot0;
            float s1 = S.cbn[c + 1] - 2.f * dot1;
            if (s0 < best) { best = s0; bi = c; }
            if (s1 < best) { best = s1; bi = c + 1; }
        }
        g_used[s * KC + bi] = 1;

        const ull* crow = S.cb2 + (size_t)bi * 64;
        #pragma unroll
        for (int i = 0; i < 64; i++) {
            float rl, rh, cl, ch;
            unpack2(rem[i], rl, rh);
            unpack2(crow[i], cl, ch);
            rl -= cl; rh -= ch;
            sq = fmaf(rl, rl, sq); sq = fmaf(rh, rh, sq);
            rem[i] = pack2(rl, rh);
        }
    }
    #pragma unroll
    for (int i = 0; i < 64; i++) {
        float rl, rh; unpack2(rem[i], rl, rh);
        g_restoredT[(2 * i) * (size_t)N_PTS + m] =
            g_latentT[(2 * i) * (size_t)N_PTS + m] - rl;
        g_restoredT[(2 * i + 1) * (size_t)N_PTS + m] =
            g_latentT[(2 * i + 1) * (size_t)N_PTS + m] - rh;
    }
    float tot = warp_sum(sq);
    if ((tid & 31) == 0) atomicAdd(&g_remsq, (double)tot);
}

// ---------------- GEMM2 (HMMA bf16x3) + fused MSE --------------------------
// C[m][n] = sum_k restored[m][k] * W_dec[n][k]; accumulate (C - emb)^2.
__global__ void __launch_bounds__(256, 1)
k_gemm2(const float* __restrict__ emb, const float* __restrict__ W_dec) {
    char* A0h = smem_raw;
    char* A0l = smem_raw + 16384;
    char* A1h = smem_raw + 32768;
    char* A1l = smem_raw + 49152;
    char* Bh  = smem_raw + 65536;
    char* Bl  = smem_raw + 81920;
    const int tid = threadIdx.x, lane = tid & 31, wid = tid >> 5;
    const int n0 = blockIdx.x * 128, m0 = blockIdx.y * 128;
    const int wm = (wid >> 1) * 32, wn = (wid & 1) * 64;
    const int r = tid >> 1, half = tid & 1;

    stage_colmajor_split(g_restoredT, m0, 0,  A0h, A0l, tid);
    stage_colmajor_split(g_restoredT, m0, 64, A1h, A1l, tid);

    float acc[2][8][4];
    #pragma unroll
    for (int i = 0; i < 2; i++)
        #pragma unroll
        for (int j = 0; j < 8; j++)
            #pragma unroll
            for (int k = 0; k < 4; k++) acc[i][j][k] = 0.f;

    for (int ch = 0; ch < 2; ch++) {
        if (ch) __syncthreads();  // previous-chunk B readers done
        #pragma unroll
        for (int q = 0; q < 8; q++) {
            float4 vb = reinterpret_cast<const float4*>(
                W_dec + (size_t)(n0 + r) * 128 + ch * 64 + half * 32)[q];
            sts_split4(vb, r, half * 32 + q * 4, Bh, Bl);
        }
        __syncthreads();
        mma_chunk(acc, ch ? A1h : A0h, ch ? A1l : A0l, Bh, Bl, wm, wn, lane);
    }

    // fused MSE epilogue
    float sq = 0.f;
    #pragma unroll
    for (int mt = 0; mt < 2; mt++) {
        int m = m0 + wm + mt * 16 + (lane >> 2);
        #pragma unroll
        for (int nt = 0; nt < 8; nt++) {
            int n = n0 + wn + nt * 8 + (lane & 3) * 2;
            float2 e0 = *reinterpret_cast<const float2*>(emb + (size_t)m * 512 + n);
            float2 e1 = *reinterpret_cast<const float2*>(emb + (size_t)(m + 8) * 512 + n);
            float d0 = acc[mt][nt][0] - e0.x;
            float d1 = acc[mt][nt][1] - e0.y;
            float d2 = acc[mt][nt][2] - e1.x;
            float d3 = acc[mt][nt][3] - e1.y;
            sq = fmaf(d0, d0, sq); sq = fmaf(d1, d1, sq);
            sq = fmaf(d2, d2, sq); sq = fmaf(d3, d3, sq);
        }
    }
    float tot = warp_sum(sq);
    if ((lane & 31) == 0) atomicAdd(&g_reconsq, (double)tot);
}

// ---------------- K4: finalize ---------------------------------------------
__global__ void k_final(float* __restrict__ out, int out_size) {
    __shared__ float vals[6];
    int tid = threadIdx.x;
    if (tid == 0) {
        double recon = g_reconsq / ((double)N_PTS * (double)D_IN);
        double rq    = 1.25 * g_remsq / ((double)N_PTS * (double)D_H);
        vals[0] = (float)(recon + rq);
        vals[1] = (float)recon;
        vals[2] = (float)rq;
    }
    if (tid < 3) {
        int cnt = 0;
        for (int c = 0; c < KC; c++) cnt += g_used[tid * KC + c];
        vals[3 + tid] = (float)cnt;
    }
    __syncthreads();
    if (tid < 6 && tid < out_size) out[tid] = vals[tid];
}

// ---------------- launch ----------------------------------------------------
extern "C" void kernel_launch(void* const* d_in, const int* in_sizes, int n_in,
                              void* d_out, int out_size) {
    const float* emb   = (const float*)d_in[0];
    const float* W_enc = (const float*)d_in[1];
    const float* W_dec = (const float*)d_in[2];
    const float* cb0   = (const float*)d_in[3];
    const float* cb1   = (const float*)d_in[4];
    const float* cb2   = (const float*)d_in[5];
    float* out = (float*)d_out;

    cudaFuncSetAttribute(k_gemm1, cudaFuncAttributeMaxDynamicSharedMemorySize, 65536);
    cudaFuncSetAttribute(k_gemm2, cudaFuncAttributeMaxDynamicSharedMemorySize, 98304);
    cudaFuncSetAttribute(k_stages, cudaFuncAttributeMaxDynamicSharedMemorySize,
                         (int)sizeof(SmemStg));

    k_init<<<3, 256>>>(cb0, cb1, cb2);
    k_gemm1<<<N_PTS / 128, 256, 65536>>>(emb, W_enc);
    k_stages<<<N_PTS / 256, 256, sizeof(SmemStg)>>>(cb0, cb1, cb2);
    k_gemm2<<<dim3(4, N_PTS / 128), 256, 98304>>>(emb, W_dec);
    k_final<<<1, 32>>>(out, out_size);
}

// round 12
// speedup vs baseline: 2.3934x; 1.4773x over previous
#include <cuda_runtime.h>
#include <cuda_bf16.h>
#include <cstdint>

#define N_PTS 131072
#define D_IN  512
#define D_H   128
#define KC    256

typedef unsigned long long ull;

// ---------------- scratch (device globals; no allocation allowed) ----------
__device__ float  g_latentT[D_H * N_PTS];    // [d][m]
__device__ float  g_restoredT[D_H * N_PTS];  // [d][m]
__device__ float  g_cbnorm[3 * KC];
__device__ int    g_used[3 * KC];
__device__ double g_remsq;
__device__ double g_reconsq;

extern __shared__ char smem_raw[];

#define SMEM_SWIZZLE_128B(bo) ((bo) ^ (((bo) >> 3) & 0x70))

// ---------------- generic helpers ------------------------------------------
__device__ __forceinline__ uint32_t smem_to_u32(const void* p) {
    uint32_t a;
    asm("{ .reg .u64 t; cvta.to.shared.u64 t, %1; cvt.u32.u64 %0, t; }"
        : "=r"(a) : "l"(p));
    return a;
}
__device__ __forceinline__ float warp_sum(float v) {
    #pragma unroll
    for (int o = 16; o; o >>= 1) v += __shfl_xor_sync(0xffffffffu, v, o);
    return v;
}

// ---------------- mma.sync helpers (family-safe HMMA path) ------------------
__device__ __forceinline__ void ldmx4(uint32_t* r, uint32_t addr) {
    asm volatile("ldmatrix.sync.aligned.m8n8.x4.shared.b16 {%0,%1,%2,%3}, [%4];"
        : "=r"(r[0]), "=r"(r[1]), "=r"(r[2]), "=r"(r[3]) : "r"(addr));
}
__device__ __forceinline__ void mma16816(float* c, const uint32_t* a, const uint32_t* b) {
    asm volatile(
        "mma.sync.aligned.m16n8k16.row.col.f32.bf16.bf16.f32 "
        "{%0,%1,%2,%3}, {%4,%5,%6,%7}, {%8,%9}, {%0,%1,%2,%3};"
        : "+f"(c[0]), "+f"(c[1]), "+f"(c[2]), "+f"(c[3])
        : "r"(a[0]), "r"(a[1]), "r"(a[2]), "r"(a[3]), "r"(b[0]), "r"(b[1]));
}

// Convert one float4 (4 consecutive k of one row) into bf16 hi/lo tiles.
// Tile rows are 128 bytes (64 bf16), XOR-swizzled.
__device__ __forceinline__ void sts_split4(float4 v, int r, int kk, char* dh, char* dl) {
    uint32_t off = SMEM_SWIZZLE_128B((uint32_t)(r * 128 + kk * 2));
    __nv_bfloat162 h01 = __float22bfloat162_rn(make_float2(v.x, v.y));
    __nv_bfloat162 h23 = __float22bfloat162_rn(make_float2(v.z, v.w));
    float2 f01 = __bfloat1622float2(h01);
    float2 f23 = __bfloat1622float2(h23);
    __nv_bfloat162 l01 = __float22bfloat162_rn(make_float2(v.x - f01.x, v.y - f01.y));
    __nv_bfloat162 l23 = __float22bfloat162_rn(make_float2(v.z - f23.x, v.w - f23.y));
    uint2 hh, ll;
    hh.x = *reinterpret_cast<uint32_t*>(&h01);
    hh.y = *reinterpret_cast<uint32_t*>(&h23);
    ll.x = *reinterpret_cast<uint32_t*>(&l01);
    ll.y = *reinterpret_cast<uint32_t*>(&l23);
    *reinterpret_cast<uint2*>(dh + off) = hh;
    *reinterpret_cast<uint2*>(dl + off) = ll;
}

// Stage A[m][k] 128x64 from K-major source srcT[k][m] into bf16 hi/lo tiles.
__device__ __forceinline__ void stage_colmajor_split(
    const float* __restrict__ srcT, int m0, int k0,
    char* dh, char* dl, int tid)
{
    int kr = tid & 63, mq = tid >> 6;
    const float4* p = reinterpret_cast<const float4*>(
        srcT + (size_t)(k0 + kr) * N_PTS + m0 + mq * 32);
    #pragma unroll
    for (int q = 0; q < 8; q++) {
        float4 v = p[q];
        int mb = mq * 32 + q * 4;
        float vv[4] = {v.x, v.y, v.z, v.w};
        #pragma unroll
        for (int e = 0; e < 4; e++) {
            float a = vv[e];
            __nv_bfloat16 h = __float2bfloat16(a);
            __nv_bfloat16 l = __float2bfloat16(a - __bfloat162float(h));
            uint32_t off = SMEM_SWIZZLE_128B((uint32_t)((mb + e) * 128 + kr * 2));
            *reinterpret_cast<__nv_bfloat16*>(dh + off) = h;
            *reinterpret_cast<__nv_bfloat16*>(dl + off) = l;
        }
    }
}

// One K=64 chunk, 3 split combos (AhBh, AlBh, AhBl) x 4 ksteps of K=16.
// Block tile 128m x 128n, 8 warps as 4(m) x 2(n); warp tile 32m x 64n.
__device__ __forceinline__ void mma_chunk(
    float acc[2][8][4], char* Ah, char* Al, char* Bh, char* Bl,
    int wm, int wn, int lane)
{
    uint32_t aT[3] = { smem_to_u32(Ah), smem_to_u32(Al), smem_to_u32(Ah) };
    uint32_t bT[3] = { smem_to_u32(Bh), smem_to_u32(Bh), smem_to_u32(Bl) };
    const int g = lane >> 3, rr = lane & 7;
    const int a_row = (g & 1) * 8 + rr, a_col = (g >> 1) * 8;
    const int b_row = (g >> 1) * 8 + rr, b_col = (g & 1) * 8;
    #pragma unroll
    for (int c = 0; c < 3; c++) {
        #pragma unroll
        for (int ks = 0; ks < 4; ks++) {
            const int k0 = ks * 16;
            uint32_t a[2][4], b[4][4];
            #pragma unroll
            for (int mt = 0; mt < 2; mt++) {
                int row = wm + mt * 16 + a_row;
                ldmx4(a[mt], aT[c] +
                      SMEM_SWIZZLE_128B((uint32_t)(row * 128 + (k0 + a_col) * 2)));
            }
            #pragma unroll
            for (int np = 0; np < 4; np++) {
                int n = wn + np * 16 + b_row;
                ldmx4(b[np], bT[c] +
                      SMEM_SWIZZLE_128B((uint32_t)(n * 128 + (k0 + b_col) * 2)));
            }
            #pragma unroll
            for (int mt = 0; mt < 2; mt++)
                #pragma unroll
                for (int nt = 0; nt < 8; nt++)
                    mma16816(acc[mt][nt], a[mt], &b[nt >> 1][(nt & 1) * 2]);
        }
    }
}

// ---------------- K0: init + codebook norms --------------------------------
__global__ void k_init(const float* __restrict__ cb0,
                       const float* __restrict__ cb1,
                       const float* __restrict__ cb2) {
    int i = blockIdx.x * 256 + threadIdx.x;
    if (i == 0) { g_remsq = 0.0; g_reconsq = 0.0; }
    if (i < 3 * KC) {
        g_used[i] = 0;
        const float* cb = (i < KC) ? cb0 : (i < 2 * KC ? cb1 : cb2);
        int c = i & (KC - 1);
        float s = 0.f;
        #pragma unroll 8
        for (int d = 0; d < D_H; d++) { float v = cb[c * D_H + d]; s = fmaf(v, v, s); }
        g_cbnorm[i] = s;
    }
}

// ---------------- GEMM1 (HMMA bf16x3): latentT = (emb @ W_enc^T)^T ---------
__global__ void __launch_bounds__(256, 1)
k_gemm1(const float* __restrict__ emb, const float* __restrict__ W_enc) {
    char* Ah = smem_raw;
    char* Al = smem_raw + 16384;
    char* Bh = smem_raw + 32768;
    char* Bl = smem_raw + 49152;
    const int tid = threadIdx.x, lane = tid & 31, wid = tid >> 5;
    const int m0 = blockIdx.x * 128;
    const int wm = (wid >> 1) * 32, wn = (wid & 1) * 64;
    const int r = tid >> 1, half = tid & 1;

    float acc[2][8][4];
    #pragma unroll
    for (int i = 0; i < 2; i++)
        #pragma unroll
        for (int j = 0; j < 8; j++)
            #pragma unroll
            for (int k = 0; k < 4; k++) acc[i][j][k] = 0.f;

    const float* aRow = emb + (size_t)(m0 + r) * 512 + half * 32;
    const float* bRow = W_enc + (size_t)r * 512 + half * 32;

    float4 pa[8];
    #pragma unroll
    for (int q = 0; q < 8; q++) pa[q] = reinterpret_cast<const float4*>(aRow)[q];

    for (int ch = 0; ch < 8; ch++) {
        #pragma unroll
        for (int q = 0; q < 8; q++) {
            sts_split4(pa[q], r, half * 32 + q * 4, Ah, Al);
            float4 vb = reinterpret_cast<const float4*>(bRow + ch * 64)[q];
            sts_split4(vb, r, half * 32 + q * 4, Bh, Bl);
        }
        __syncthreads();
        if (ch < 7) {
            #pragma unroll
            for (int q = 0; q < 8; q++)
                pa[q] = reinterpret_cast<const float4*>(aRow + (ch + 1) * 64)[q];
        }
        mma_chunk(acc, Ah, Al, Bh, Bl, wm, wn, lane);
        __syncthreads();
    }

    #pragma unroll
    for (int mt = 0; mt < 2; mt++) {
        int m = m0 + wm + mt * 16 + (lane >> 2);
        #pragma unroll
        for (int nt = 0; nt < 8; nt++) {
            int n = wn + nt * 8 + (lane & 3) * 2;
            g_latentT[(size_t)n * N_PTS + m]           = acc[mt][nt][0];
            g_latentT[(size_t)(n + 1) * N_PTS + m]     = acc[mt][nt][1];
            g_latentT[(size_t)n * N_PTS + m + 8]       = acc[mt][nt][2];
            g_latentT[(size_t)(n + 1) * N_PTS + m + 8] = acc[mt][nt][3];
        }
    }
}

// ---------------- K2: fused 3-stage RQ via HMMA distance GEMM --------------
// CTA = 128 points. remF (fp32) lives in smem across stages; per stage:
// dots = rem @ cb^T (bf16x3 mma), score = ||c||^2 - 2 dot, argmin, exact
// fp32 remainder update from gmem codebook.
struct SmemStg2 {
    float remF[128][132];       // fp32 remainder, padded rows
    char  Ah[16384];            // A 128x64 bf16 hi
    char  Al[16384];            // A lo
    char  Bh[32768];            // B 256x64 bf16 hi
    char  Bl[32768];            // B lo
    float cbn[KC];
    float bestS[2][128];
    int   bestI[2][128];
};

__global__ void __launch_bounds__(256, 1)
k_stages(const float* __restrict__ cb0, const float* __restrict__ cb1,
         const float* __restrict__ cb2g) {
    SmemStg2& S = *reinterpret_cast<SmemStg2*>(smem_raw);
    const int tid = threadIdx.x, lane = tid & 31, wid = tid >> 5;
    const int m0 = blockIdx.x * 128;
    const int wm = (wid >> 1) * 32;        // 4 m-groups of 32
    const int wn = (wid & 1) * 128;        // 2 n-groups of 128

    // load latent -> remF (coalesced gmem read along m)
    for (int idx = tid; idx < 128 * 128; idx += 256) {
        int m = idx & 127, k = idx >> 7;
        S.remF[m][k] = g_latentT[(size_t)k * N_PTS + m0 + m];
    }

    float sq = 0.f;
    for (int s = 0; s < 3; s++) {
        const float* cb = (s == 0) ? cb0 : (s == 1 ? cb1 : cb2g);
        S.cbn[tid < KC ? tid : 0] = g_cbnorm[s * KC + (tid < KC ? tid : 0)];

        float acc[2][16][4];
        #pragma unroll
        for (int i = 0; i < 2; i++)
            #pragma unroll
            for (int j = 0; j < 16; j++)
                #pragma unroll
                for (int k = 0; k < 4; k++) acc[i][j][k] = 0.f;

        for (int chunk = 0; chunk < 2; chunk++) {
            __syncthreads();   // prior readers of tiles / remF update done
            // stage A (rem) 128x64 from remF
            #pragma unroll
            for (int i = 0; i < 8; i++) {
                int idx = tid + i * 256;
                int r = idx >> 4, f4 = idx & 15;
                float4 v = *reinterpret_cast<const float4*>(
                    &S.remF[r][chunk * 64 + f4 * 4]);
                sts_split4(v, r, f4 * 4, S.Ah, S.Al);
            }
            // stage B (codebook) 256x64 from gmem (coalesced 16 thr/row)
            #pragma unroll
            for (int i = 0; i < 16; i++) {
                int idx = tid + i * 256;
                int n = idx >> 4, f4 = idx & 15;
                float4 v = *reinterpret_cast<const float4*>(
                    cb + (size_t)n * 128 + chunk * 64 + f4 * 4);
                sts_split4(v, n, f4 * 4, S.Bh, S.Bl);
            }
            __syncthreads();

            // mma: 3 combos x 4 ksteps; warp tile 32m x 128n
            uint32_t aT[3] = { smem_to_u32(S.Ah), smem_to_u32(S.Al), smem_to_u32(S.Ah) };
            uint32_t bT[3] = { smem_to_u32(S.Bh), smem_to_u32(S.Bh), smem_to_u32(S.Bl) };
            const int g = lane >> 3, rr = lane & 7;
            const int a_row = (g & 1) * 8 + rr, a_col = (g >> 1) * 8;
            const int b_row = (g >> 1) * 8 + rr, b_col = (g & 1) * 8;
            #pragma unroll
            for (int c = 0; c < 3; c++) {
                #pragma unroll
                for (int ks = 0; ks < 4; ks++) {
                    const int k0 = ks * 16;
                    uint32_t a[2][4], b[8][4];
                    #pragma unroll
                    for (int mt = 0; mt < 2; mt++) {
                        int row = wm + mt * 16 + a_row;
                        ldmx4(a[mt], aT[c] +
                              SMEM_SWIZZLE_128B((uint32_t)(row * 128 + (k0 + a_col) * 2)));
                    }
                    #pragma unroll
                    for (int np = 0; np < 8; np++) {
                        int n = wn + np * 16 + b_row;
                        ldmx4(b[np], bT[c] +
                              SMEM_SWIZZLE_128B((uint32_t)(n * 128 + (k0 + b_col) * 2)));
                    }
                    #pragma unroll
                    for (int mt = 0; mt < 2; mt++)
                        #pragma unroll
                        for (int nt = 0; nt < 16; nt++)
                            mma16816(acc[mt][nt], a[mt], &b[nt >> 1][(nt & 1) * 2]);
                }
            }
        }

        // ---- argmin: score = cbn[n] - 2*dot ----
        float bs[2][2]; int bn[2][2];
        #pragma unroll
        for (int mt = 0; mt < 2; mt++)
            #pragma unroll
            for (int rh = 0; rh < 2; rh++) { bs[mt][rh] = 3.4e38f; bn[mt][rh] = 0; }
        #pragma unroll
        for (int nt = 0; nt < 16; nt++) {
            #pragma unroll
            for (int mt = 0; mt < 2; mt++)
                #pragma unroll
                for (int rh = 0; rh < 2; rh++)
                    #pragma unroll
                    for (int e = 0; e < 2; e++) {
                        int n = wn + nt * 8 + (lane & 3) * 2 + e;
                        float sc = S.cbn[n] - 2.f * acc[mt][nt][rh * 2 + e];
                        if (sc < bs[mt][rh] ||
                            (sc == bs[mt][rh] && n < bn[mt][rh])) {
                            bs[mt][rh] = sc; bn[mt][rh] = n;
                        }
                    }
        }
        #pragma unroll
        for (int o = 1; o < 4; o <<= 1) {
            #pragma unroll
            for (int mt = 0; mt < 2; mt++)
                #pragma unroll
                for (int rh = 0; rh < 2; rh++) {
                    float so = __shfl_xor_sync(0xffffffffu, bs[mt][rh], o);
                    int   no = __shfl_xor_sync(0xffffffffu, bn[mt][rh], o);
                    if (so < bs[mt][rh] ||
                        (so == bs[mt][rh] && no < bn[mt][rh])) {
                        bs[mt][rh] = so; bn[mt][rh] = no;
                    }
                }
        }
        if ((lane & 3) == 0) {
            #pragma unroll
            for (int mt = 0; mt < 2; mt++)
                #pragma unroll
                for (int rh = 0; rh < 2; rh++) {
                    int ml = wm + mt * 16 + (lane >> 2) + rh * 8;
                    S.bestS[wid & 1][ml] = bs[mt][rh];
                    S.bestI[wid & 1][ml] = bn[mt][rh];
                }
        }
        __syncthreads();

        // ---- exact fp32 remainder update + loss accumulation ----
        {
            int m = tid >> 1, kh = tid & 1;
            float s0 = S.bestS[0][m], s1 = S.bestS[1][m];
            int bi = (s1 < s0) ? S.bestI[1][m] : S.bestI[0][m];
            if (kh == 0) g_used[s * KC + bi] = 1;
            const float4* crow = reinterpret_cast<const float4*>(
                cb + (size_t)bi * 128 + kh * 64);
            float4* rrow = reinterpret_cast<float4*>(&S.remF[m][kh * 64]);
            #pragma unroll
            for (int q = 0; q < 16; q++) {
                float4 cv = crow[q];
                float4 rv = rrow[q];
                rv.x -= cv.x; rv.y -= cv.y; rv.z -= cv.z; rv.w -= cv.w;
                sq = fmaf(rv.x, rv.x, sq); sq = fmaf(rv.y, rv.y, sq);
                sq = fmaf(rv.z, rv.z, sq); sq = fmaf(rv.w, rv.w, sq);
                rrow[q] = rv;
            }
        }
    }
    __syncthreads();

    // restored = latent - rem_final  (coalesced along m)
    for (int idx = tid; idx < 128 * 128; idx += 256) {
        int m = idx & 127, k = idx >> 7;
        g_restoredT[(size_t)k * N_PTS + m0 + m] =
            g_latentT[(size_t)k * N_PTS + m0 + m] - S.remF[m][k];
    }
    float tot = warp_sum(sq);
    if (lane == 0) atomicAdd(&g_remsq, (double)tot);
}

// ---------------- GEMM2 (HMMA bf16x3) + fused MSE --------------------------
__global__ void __launch_bounds__(256, 1)
k_gemm2(const float* __restrict__ emb, const float* __restrict__ W_dec) {
    char* A0h = smem_raw;
    char* A0l = smem_raw + 16384;
    char* A1h = smem_raw + 32768;
    char* A1l = smem_raw + 49152;
    char* Bh  = smem_raw + 65536;
    char* Bl  = smem_raw + 81920;
    const int tid = threadIdx.x, lane = tid & 31, wid = tid >> 5;
    const int n0 = blockIdx.x * 128, m0 = blockIdx.y * 128;
    const int wm = (wid >> 1) * 32, wn = (wid & 1) * 64;
    const int r = tid >> 1, half = tid & 1;

    stage_colmajor_split(g_restoredT, m0, 0,  A0h, A0l, tid);
    stage_colmajor_split(g_restoredT, m0, 64, A1h, A1l, tid);

    float acc[2][8][4];
    #pragma unroll
    for (int i = 0; i < 2; i++)
        #pragma unroll
        for (int j = 0; j < 8; j++)
            #pragma unroll
            for (int k = 0; k < 4; k++) acc[i][j][k] = 0.f;

    for (int ch = 0; ch < 2; ch++) {
        if (ch) __syncthreads();
        #pragma unroll
        for (int q = 0; q < 8; q++) {
            float4 vb = reinterpret_cast<const float4*>(
                W_dec + (size_t)(n0 + r) * 128 + ch * 64 + half * 32)[q];
            sts_split4(vb, r, half * 32 + q * 4, Bh, Bl);
        }
        __syncthreads();
        mma_chunk(acc, ch ? A1h : A0h, ch ? A1l : A0l, Bh, Bl, wm, wn, lane);
    }

    float sq = 0.f;
    #pragma unroll
    for (int mt = 0; mt < 2; mt++) {
        int m = m0 + wm + mt * 16 + (lane >> 2);
        #pragma unroll
        for (int nt = 0; nt < 8; nt++) {
            int n = n0 + wn + nt * 8 + (lane & 3) * 2;
            float2 e0 = *reinterpret_cast<const float2*>(emb + (size_t)m * 512 + n);
            float2 e1 = *reinterpret_cast<const float2*>(emb + (size_t)(m + 8) * 512 + n);
            float d0 = acc[mt][nt][0] - e0.x;
            float d1 = acc[mt][nt][1] - e0.y;
            float d2 = acc[mt][nt][2] - e1.x;
            float d3 = acc[mt][nt][3] - e1.y;
            sq = fmaf(d0, d0, sq); sq = fmaf(d1, d1, sq);
            sq = fmaf(d2, d2, sq); sq = fmaf(d3, d3, sq);
        }
    }
    float tot = warp_sum(sq);
    if ((lane & 31) == 0) atomicAdd(&g_reconsq, (double)tot);
}

// ---------------- K4: finalize ---------------------------------------------
__global__ void k_final(float* __restrict__ out, int out_size) {
    __shared__ float vals[6];
    int tid = threadIdx.x;
    if (tid == 0) {
        double recon = g_reconsq / ((double)N_PTS * (double)D_IN);
        double rq    = 1.25 * g_remsq / ((double)N_PTS * (double)D_H);
        vals[0] = (float)(recon + rq);
        vals[1] = (float)recon;
        vals[2] = (float)rq;
    }
    if (tid < 3) {
        int cnt = 0;
        for (int c = 0; c < KC; c++) cnt += g_used[tid * KC + c];
        vals[3 + tid] = (float)cnt;
    }
    __syncthreads();
    if (tid < 6 && tid < out_size) out[tid] = vals[tid];
}

// ---------------- launch ----------------------------------------------------
extern "C" void kernel_launch(void* const* d_in, const int* in_sizes, int n_in,
                              void* d_out, int out_size) {
    const float* emb   = (const float*)d_in[0];
    const float* W_enc = (const float*)d_in[1];
    const float* W_dec = (const float*)d_in[2];
    const float* cb0   = (const float*)d_in[3];
    const float* cb1   = (const float*)d_in[4];
    const float* cb2   = (const float*)d_in[5];
    float* out = (float*)d_out;

    cudaFuncSetAttribute(k_gemm1, cudaFuncAttributeMaxDynamicSharedMemorySize, 65536);
    cudaFuncSetAttribute(k_gemm2, cudaFuncAttributeMaxDynamicSharedMemorySize, 98304);
    cudaFuncSetAttribute(k_stages, cudaFuncAttributeMaxDynamicSharedMemorySize,
                         (int)sizeof(SmemStg2));

    k_init<<<3, 256>>>(cb0, cb1, cb2);
    k_gemm1<<<N_PTS / 128, 256, 65536>>>(emb, W_enc);
    k_stages<<<N_PTS / 128, 256, sizeof(SmemStg2)>>>(cb0, cb1, cb2);
    k_gemm2<<<dim3(4, N_PTS / 128), 256, 98304>>>(emb, W_dec);
    k_final<<<1, 32>>>(out, out_size);
}

// round 13
// speedup vs baseline: 2.6961x; 1.1265x over previous
#include <cuda_runtime.h>
#include <cuda_bf16.h>
#include <cstdint>

#define N_PTS 131072
#define D_IN  512
#define D_H   128
#define KC    256

typedef unsigned long long ull;

// ---------------- scratch (device globals; no allocation allowed) ----------
__device__ float  g_latentT[D_H * N_PTS];    // [d][m]
__device__ float  g_restoredT[D_H * N_PTS];  // [d][m]
__device__ float  g_cbnorm[3 * KC];
__device__ int    g_used[3 * KC];
__device__ double g_remsq;
__device__ double g_reconsq;

extern __shared__ char smem_raw[];

#define SMEM_SWIZZLE_128B(bo) ((bo) ^ (((bo) >> 3) & 0x70))

// ---------------- generic helpers ------------------------------------------
__device__ __forceinline__ uint32_t smem_to_u32(const void* p) {
    uint32_t a;
    asm("{ .reg .u64 t; cvta.to.shared.u64 t, %1; cvt.u32.u64 %0, t; }"
        : "=r"(a) : "l"(p));
    return a;
}
__device__ __forceinline__ float warp_sum(float v) {
    #pragma unroll
    for (int o = 16; o; o >>= 1) v += __shfl_xor_sync(0xffffffffu, v, o);
    return v;
}

// ---------------- mma.sync helpers (family-safe HMMA path) ------------------
__device__ __forceinline__ void ldmx4(uint32_t* r, uint32_t addr) {
    asm volatile("ldmatrix.sync.aligned.m8n8.x4.shared.b16 {%0,%1,%2,%3}, [%4];"
        : "=r"(r[0]), "=r"(r[1]), "=r"(r[2]), "=r"(r[3]) : "r"(addr));
}
__device__ __forceinline__ void mma16816(float* c, const uint32_t* a, const uint32_t* b) {
    asm volatile(
        "mma.sync.aligned.m16n8k16.row.col.f32.bf16.bf16.f32 "
        "{%0,%1,%2,%3}, {%4,%5,%6,%7}, {%8,%9}, {%0,%1,%2,%3};"
        : "+f"(c[0]), "+f"(c[1]), "+f"(c[2]), "+f"(c[3])
        : "r"(a[0]), "r"(a[1]), "r"(a[2]), "r"(a[3]), "r"(b[0]), "r"(b[1]));
}

// Convert one float4 (4 consecutive k of one row) into bf16 hi/lo tiles.
// Tile rows are 128 bytes (64 bf16), XOR-swizzled.
__device__ __forceinline__ void sts_split4(float4 v, int r, int kk, char* dh, char* dl) {
    uint32_t off = SMEM_SWIZZLE_128B((uint32_t)(r * 128 + kk * 2));
    __nv_bfloat162 h01 = __float22bfloat162_rn(make_float2(v.x, v.y));
    __nv_bfloat162 h23 = __float22bfloat162_rn(make_float2(v.z, v.w));
    float2 f01 = __bfloat1622float2(h01);
    float2 f23 = __bfloat1622float2(h23);
    __nv_bfloat162 l01 = __float22bfloat162_rn(make_float2(v.x - f01.x, v.y - f01.y));
    __nv_bfloat162 l23 = __float22bfloat162_rn(make_float2(v.z - f23.x, v.w - f23.y));
    uint2 hh, ll;
    hh.x = *reinterpret_cast<uint32_t*>(&h01);
    hh.y = *reinterpret_cast<uint32_t*>(&h23);
    ll.x = *reinterpret_cast<uint32_t*>(&l01);
    ll.y = *reinterpret_cast<uint32_t*>(&l23);
    *reinterpret_cast<uint2*>(dh + off) = hh;
    *reinterpret_cast<uint2*>(dl + off) = ll;
}

// Stage A[m][k] 128x64 from K-major source srcT[k][m] into bf16 hi/lo tiles.
__device__ __forceinline__ void stage_colmajor_split(
    const float* __restrict__ srcT, int m0, int k0,
    char* dh, char* dl, int tid)
{
    int kr = tid & 63, mq = tid >> 6;
    const float4* p = reinterpret_cast<const float4*>(
        srcT + (size_t)(k0 + kr) * N_PTS + m0 + mq * 32);
    #pragma unroll
    for (int q = 0; q < 8; q++) {
        float4 v = p[q];
        int mb = mq * 32 + q * 4;
        float vv[4] = {v.x, v.y, v.z, v.w};
        #pragma unroll
        for (int e = 0; e < 4; e++) {
            float a = vv[e];
            __nv_bfloat16 h = __float2bfloat16(a);
            __nv_bfloat16 l = __float2bfloat16(a - __bfloat162float(h));
            uint32_t off = SMEM_SWIZZLE_128B((uint32_t)((mb + e) * 128 + kr * 2));
            *reinterpret_cast<__nv_bfloat16*>(dh + off) = h;
            *reinterpret_cast<__nv_bfloat16*>(dl + off) = l;
        }
    }
}

// One K=64 chunk with hoisted fragment loads: per kstep load ah/al once,
// per 16-n tile load bh/bl once, issue 3 split-combo MMAs from registers.
// Warp tile 32m x 64n.
__device__ __forceinline__ void mma_chunk2(
    float acc[2][8][4], char* Ah, char* Al, char* Bh, char* Bl,
    int wm, int wn, int lane)
{
    uint32_t ahB = smem_to_u32(Ah), alB = smem_to_u32(Al);
    uint32_t bhB = smem_to_u32(Bh), blB = smem_to_u32(Bl);
    const int g = lane >> 3, rr = lane & 7;
    const int a_row = (g & 1) * 8 + rr, a_col = (g >> 1) * 8;
    const int b_row = (g >> 1) * 8 + rr, b_col = (g & 1) * 8;
    #pragma unroll
    for (int ks = 0; ks < 4; ks++) {
        const int k0 = ks * 16;
        uint32_t ah[2][4], al[2][4];
        #pragma unroll
        for (int mt = 0; mt < 2; mt++) {
            uint32_t off = SMEM_SWIZZLE_128B(
                (uint32_t)((wm + mt * 16 + a_row) * 128 + (k0 + a_col) * 2));
            ldmx4(ah[mt], ahB + off);
            ldmx4(al[mt], alB + off);
        }
        #pragma unroll
        for (int np = 0; np < 4; np++) {
            uint32_t bh[4], bl[4];
            uint32_t off = SMEM_SWIZZLE_128B(
                (uint32_t)((wn + np * 16 + b_row) * 128 + (k0 + b_col) * 2));
            ldmx4(bh, bhB + off);
            ldmx4(bl, blB + off);
            #pragma unroll
            for (int mt = 0; mt < 2; mt++)
                #pragma unroll
                for (int h = 0; h < 2; h++) {
                    float* c = acc[mt][np * 2 + h];
                    mma16816(c, ah[mt], bh + h * 2);
                    mma16816(c, al[mt], bh + h * 2);
                    mma16816(c, ah[mt], bl + h * 2);
                }
        }
    }
}

// ---------------- K0: init + codebook norms --------------------------------
__global__ void k_init(const float* __restrict__ cb0,
                       const float* __restrict__ cb1,
                       const float* __restrict__ cb2) {
    int i = blockIdx.x * 256 + threadIdx.x;
    if (i == 0) { g_remsq = 0.0; g_reconsq = 0.0; }
    if (i < 3 * KC) {
        g_used[i] = 0;
        const float* cb = (i < KC) ? cb0 : (i < 2 * KC ? cb1 : cb2);
        int c = i & (KC - 1);
        float s = 0.f;
        #pragma unroll 8
        for (int d = 0; d < D_H; d++) { float v = cb[c * D_H + d]; s = fmaf(v, v, s); }
        g_cbnorm[i] = s;
    }
}

// ---------------- GEMM1 (HMMA bf16x3): latentT = (emb @ W_enc^T)^T ---------
__global__ void __launch_bounds__(256, 1)
k_gemm1(const float* __restrict__ emb, const float* __restrict__ W_enc) {
    char* Ah = smem_raw;
    char* Al = smem_raw + 16384;
    char* Bh = smem_raw + 32768;
    char* Bl = smem_raw + 49152;
    const int tid = threadIdx.x, lane = tid & 31, wid = tid >> 5;
    const int m0 = blockIdx.x * 128;
    const int wm = (wid >> 1) * 32, wn = (wid & 1) * 64;
    const int r = tid >> 1, half = tid & 1;

    float acc[2][8][4];
    #pragma unroll
    for (int i = 0; i < 2; i++)
        #pragma unroll
        for (int j = 0; j < 8; j++)
            #pragma unroll
            for (int k = 0; k < 4; k++) acc[i][j][k] = 0.f;

    const float* aRow = emb + (size_t)(m0 + r) * 512 + half * 32;
    const float* bRow = W_enc + (size_t)r * 512 + half * 32;

    float4 pa[8];
    #pragma unroll
    for (int q = 0; q < 8; q++) pa[q] = reinterpret_cast<const float4*>(aRow)[q];

    for (int ch = 0; ch < 8; ch++) {
        #pragma unroll
        for (int q = 0; q < 8; q++) {
            sts_split4(pa[q], r, half * 32 + q * 4, Ah, Al);
            float4 vb = reinterpret_cast<const float4*>(bRow + ch * 64)[q];
            sts_split4(vb, r, half * 32 + q * 4, Bh, Bl);
        }
        __syncthreads();
        if (ch < 7) {
            #pragma unroll
            for (int q = 0; q < 8; q++)
                pa[q] = reinterpret_cast<const float4*>(aRow + (ch + 1) * 64)[q];
        }
        mma_chunk2(acc, Ah, Al, Bh, Bl, wm, wn, lane);
        __syncthreads();
    }

    #pragma unroll
    for (int mt = 0; mt < 2; mt++) {
        int m = m0 + wm + mt * 16 + (lane >> 2);
        #pragma unroll
        for (int nt = 0; nt < 8; nt++) {
            int n = wn + nt * 8 + (lane & 3) * 2;
            g_latentT[(size_t)n * N_PTS + m]           = acc[mt][nt][0];
            g_latentT[(size_t)(n + 1) * N_PTS + m]     = acc[mt][nt][1];
            g_latentT[(size_t)n * N_PTS + m + 8]       = acc[mt][nt][2];
            g_latentT[(size_t)(n + 1) * N_PTS + m + 8] = acc[mt][nt][3];
        }
    }
}

// ---------------- K2: fused 3-stage RQ via HMMA distance GEMM --------------
struct SmemStg2 {
    float remF[128][132];       // fp32 remainder, padded rows
    char  Ah[16384];            // A 128x64 bf16 hi
    char  Al[16384];            // A lo
    char  Bh[32768];            // B 256x64 bf16 hi
    char  Bl[32768];            // B lo
    float cbn[KC];
    float bestS[2][128];
    int   bestI[2][128];
};

__global__ void __launch_bounds__(256, 1)
k_stages(const float* __restrict__ cb0, const float* __restrict__ cb1,
         const float* __restrict__ cb2g) {
    SmemStg2& S = *reinterpret_cast<SmemStg2*>(smem_raw);
    const int tid = threadIdx.x, lane = tid & 31, wid = tid >> 5;
    const int m0 = blockIdx.x * 128;
    const int wm = (wid >> 1) * 32;        // 4 m-groups of 32
    const int wn = (wid & 1) * 128;        // 2 n-groups of 128

    for (int idx = tid; idx < 128 * 128; idx += 256) {
        int m = idx & 127, k = idx >> 7;
        S.remF[m][k] = g_latentT[(size_t)k * N_PTS + m0 + m];
    }

    float sq = 0.f;
    for (int s = 0; s < 3; s++) {
        const float* cb = (s == 0) ? cb0 : (s == 1 ? cb1 : cb2g);
        S.cbn[tid < KC ? tid : 0] = g_cbnorm[s * KC + (tid < KC ? tid : 0)];

        float acc[2][16][4];
        #pragma unroll
        for (int i = 0; i < 2; i++)
            #pragma unroll
            for (int j = 0; j < 16; j++)
                #pragma unroll
                for (int k = 0; k < 4; k++) acc[i][j][k] = 0.f;

        for (int chunk = 0; chunk < 2; chunk++) {
            __syncthreads();   // prior readers of tiles / remF update done
            #pragma unroll
            for (int i = 0; i < 8; i++) {
                int idx = tid + i * 256;
                int r = idx >> 4, f4 = idx & 15;
                float4 v = *reinterpret_cast<const float4*>(
                    &S.remF[r][chunk * 64 + f4 * 4]);
                sts_split4(v, r, f4 * 4, S.Ah, S.Al);
            }
            #pragma unroll
            for (int i = 0; i < 16; i++) {
                int idx = tid + i * 256;
                int n = idx >> 4, f4 = idx & 15;
                float4 v = *reinterpret_cast<const float4*>(
                    cb + (size_t)n * 128 + chunk * 64 + f4 * 4);
                sts_split4(v, n, f4 * 4, S.Bh, S.Bl);
            }
            __syncthreads();

            // hoisted-fragment mma: warp tile 32m x 128n
            uint32_t ahB = smem_to_u32(S.Ah), alB = smem_to_u32(S.Al);
            uint32_t bhB = smem_to_u32(S.Bh), blB = smem_to_u32(S.Bl);
            const int g = lane >> 3, rr = lane & 7;
            const int a_row = (g & 1) * 8 + rr, a_col = (g >> 1) * 8;
            const int b_row = (g >> 1) * 8 + rr, b_col = (g & 1) * 8;
            #pragma unroll
            for (int ks = 0; ks < 4; ks++) {
                const int k0 = ks * 16;
                uint32_t ah[2][4], al[2][4];
                #pragma unroll
                for (int mt = 0; mt < 2; mt++) {
                    uint32_t off = SMEM_SWIZZLE_128B(
                        (uint32_t)((wm + mt * 16 + a_row) * 128 + (k0 + a_col) * 2));
                    ldmx4(ah[mt], ahB + off);
                    ldmx4(al[mt], alB + off);
                }
                #pragma unroll
                for (int np = 0; np < 8; np++) {
                    uint32_t bh[4], bl[4];
                    uint32_t off = SMEM_SWIZZLE_128B(
                        (uint32_t)((wn + np * 16 + b_row) * 128 + (k0 + b_col) * 2));
                    ldmx4(bh, bhB + off);
                    ldmx4(bl, blB + off);
                    #pragma unroll
                    for (int mt = 0; mt < 2; mt++)
                        #pragma unroll
                        for (int h = 0; h < 2; h++) {
                            float* c = acc[mt][np * 2 + h];
                            mma16816(c, ah[mt], bh + h * 2);
                            mma16816(c, al[mt], bh + h * 2);
                            mma16816(c, ah[mt], bl + h * 2);
                        }
                }
            }
        }

        // ---- argmin: score = cbn[n] - 2*dot ----
        float bs[2][2]; int bn[2][2];
        #pragma unroll
        for (int mt = 0; mt < 2; mt++)
            #pragma unroll
            for (int rh = 0; rh < 2; rh++) { bs[mt][rh] = 3.4e38f; bn[mt][rh] = 0; }
        #pragma unroll
        for (int nt = 0; nt < 16; nt++) {
            #pragma unroll
            for (int mt = 0; mt < 2; mt++)
                #pragma unroll
                for (int rh = 0; rh < 2; rh++)
                    #pragma unroll
                    for (int e = 0; e < 2; e++) {
                        int n = wn + nt * 8 + (lane & 3) * 2 + e;
                        float sc = S.cbn[n] - 2.f * acc[mt][nt][rh * 2 + e];
                        if (sc < bs[mt][rh] ||
                            (sc == bs[mt][rh] && n < bn[mt][rh])) {
                            bs[mt][rh] = sc; bn[mt][rh] = n;
                        }
                    }
        }
        #pragma unroll
        for (int o = 1; o < 4; o <<= 1) {
            #pragma unroll
            for (int mt = 0; mt < 2; mt++)
                #pragma unroll
                for (int rh = 0; rh < 2; rh++) {
                    float so = __shfl_xor_sync(0xffffffffu, bs[mt][rh], o);
                    int   no = __shfl_xor_sync(0xffffffffu, bn[mt][rh], o);
                    if (so < bs[mt][rh] ||
                        (so == bs[mt][rh] && no < bn[mt][rh])) {
                        bs[mt][rh] = so; bn[mt][rh] = no;
                    }
                }
        }
        if ((lane & 3) == 0) {
            #pragma unroll
            for (int mt = 0; mt < 2; mt++)
                #pragma unroll
                for (int rh = 0; rh < 2; rh++) {
                    int ml = wm + mt * 16 + (lane >> 2) + rh * 8;
                    S.bestS[wid & 1][ml] = bs[mt][rh];
                    S.bestI[wid & 1][ml] = bn[mt][rh];
                }
        }
        __syncthreads();

        // ---- exact fp32 remainder update + loss accumulation ----
        {
            int m = tid >> 1, kh = tid & 1;
            float s0 = S.bestS[0][m], s1 = S.bestS[1][m];
            int bi = (s1 < s0) ? S.bestI[1][m] : S.bestI[0][m];
            if (kh == 0) g_used[s * KC + bi] = 1;
            const float4* crow = reinterpret_cast<const float4*>(
                cb + (size_t)bi * 128 + kh * 64);
            float4* rrow = reinterpret_cast<float4*>(&S.remF[m][kh * 64]);
            #pragma unroll
            for (int q = 0; q < 16; q++) {
                float4 cv = crow[q];
                float4 rv = rrow[q];
                rv.x -= cv.x; rv.y -= cv.y; rv.z -= cv.z; rv.w -= cv.w;
                sq = fmaf(rv.x, rv.x, sq); sq = fmaf(rv.y, rv.y, sq);
                sq = fmaf(rv.z, rv.z, sq); sq = fmaf(rv.w, rv.w, sq);
                rrow[q] = rv;
            }
        }
    }
    __syncthreads();

    for (int idx = tid; idx < 128 * 128; idx += 256) {
        int m = idx & 127, k = idx >> 7;
        g_restoredT[(size_t)k * N_PTS + m0 + m] =
            g_latentT[(size_t)k * N_PTS + m0 + m] - S.remF[m][k];
    }
    float tot = warp_sum(sq);
    if (lane == 0) atomicAdd(&g_remsq, (double)tot);
}

// ---------------- GEMM2 (HMMA bf16x3) + fused MSE --------------------------
// One CTA per 128-m tile; loops all 4 n-tiles with A staged once.
__global__ void __launch_bounds__(256, 1)
k_gemm2(const float* __restrict__ emb, const float* __restrict__ W_dec) {
    char* A0h = smem_raw;
    char* A0l = smem_raw + 16384;
    char* A1h = smem_raw + 32768;
    char* A1l = smem_raw + 49152;
    char* B0h = smem_raw + 65536;
    char* B0l = smem_raw + 81920;
    char* B1h = smem_raw + 98304;
    char* B1l = smem_raw + 114688;
    const int tid = threadIdx.x, lane = tid & 31, wid = tid >> 5;
    const int m0 = blockIdx.x * 128;
    const int wm = (wid >> 1) * 32, wn = (wid & 1) * 64;
    const int r = tid >> 1, half = tid & 1;

    stage_colmajor_split(g_restoredT, m0, 0,  A0h, A0l, tid);
    stage_colmajor_split(g_restoredT, m0, 64, A1h, A1l, tid);

    float sq = 0.f;
    for (int nt = 0; nt < 4; nt++) {
        const int n0 = nt * 128;
        __syncthreads();  // A visible (nt=0) / previous-nt B readers done
        #pragma unroll
        for (int q = 0; q < 8; q++) {
            float4 v0 = reinterpret_cast<const float4*>(
                W_dec + (size_t)(n0 + r) * 128 + half * 32)[q];
            sts_split4(v0, r, half * 32 + q * 4, B0h, B0l);
            float4 v1 = reinterpret_cast<const float4*>(
                W_dec + (size_t)(n0 + r) * 128 + 64 + half * 32)[q];
            sts_split4(v1, r, half * 32 + q * 4, B1h, B1l);
        }
        __syncthreads();

        float acc[2][8][4];
        #pragma unroll
        for (int i = 0; i < 2; i++)
            #pragma unroll
            for (int j = 0; j < 8; j++)
                #pragma unroll
                for (int k = 0; k < 4; k++) acc[i][j][k] = 0.f;

        mma_chunk2(acc, A0h, A0l, B0h, B0l, wm, wn, lane);
        mma_chunk2(acc, A1h, A1l, B1h, B1l, wm, wn, lane);

        // fused MSE epilogue for this n-tile
        #pragma unroll
        for (int mt = 0; mt < 2; mt++) {
            int m = m0 + wm + mt * 16 + (lane >> 2);
            #pragma unroll
            for (int ntile = 0; ntile < 8; ntile++) {
                int n = n0 + wn + ntile * 8 + (lane & 3) * 2;
                float2 e0 = *reinterpret_cast<const float2*>(emb + (size_t)m * 512 + n);
                float2 e1 = *reinterpret_cast<const float2*>(emb + (size_t)(m + 8) * 512 + n);
                float d0 = acc[mt][ntile][0] - e0.x;
                float d1 = acc[mt][ntile][1] - e0.y;
                float d2 = acc[mt][ntile][2] - e1.x;
                float d3 = acc[mt][ntile][3] - e1.y;
                sq = fmaf(d0, d0, sq); sq = fmaf(d1, d1, sq);
                sq = fmaf(d2, d2, sq); sq = fmaf(d3, d3, sq);
            }
        }
    }
    float tot = warp_sum(sq);
    if (lane == 0) atomicAdd(&g_reconsq, (double)tot);
}

// ---------------- K4: finalize ---------------------------------------------
__global__ void k_final(float* __restrict__ out, int out_size) {
    __shared__ float vals[6];
    int tid = threadIdx.x;
    if (tid == 0) {
        double recon = g_reconsq / ((double)N_PTS * (double)D_IN);
        double rq    = 1.25 * g_remsq / ((double)N_PTS * (double)D_H);
        vals[0] = (float)(recon + rq);
        vals[1] = (float)recon;
        vals[2] = (float)rq;
    }
    if (tid < 3) {
        int cnt = 0;
        for (int c = 0; c < KC; c++) cnt += g_used[tid * KC + c];
        vals[3 + tid] = (float)cnt;
    }
    __syncthreads();
    if (tid < 6 && tid < out_size) out[tid] = vals[tid];
}

// ---------------- launch ----------------------------------------------------
extern "C" void kernel_launch(void* const* d_in, const int* in_sizes, int n_in,
                              void* d_out, int out_size) {
    const float* emb   = (const float*)d_in[0];
    const float* W_enc = (const float*)d_in[1];
    const float* W_dec = (const float*)d_in[2];
    const float* cb0   = (const float*)d_in[3];
    const float* cb1   = (const float*)d_in[4];
    const float* cb2   = (const float*)d_in[5];
    float* out = (float*)d_out;

    cudaFuncSetAttribute(k_gemm1, cudaFuncAttributeMaxDynamicSharedMemorySize, 65536);
    cudaFuncSetAttribute(k_gemm2, cudaFuncAttributeMaxDynamicSharedMemorySize, 131072);
    cudaFuncSetAttribute(k_stages, cudaFuncAttributeMaxDynamicSharedMemorySize,
                         (int)sizeof(SmemStg2));

    k_init<<<3, 256>>>(cb0, cb1, cb2);
    k_gemm1<<<N_PTS / 128, 256, 65536>>>(emb, W_enc);
    k_stages<<<N_PTS / 128, 256, sizeof(SmemStg2)>>>(cb0, cb1, cb2);
    k_gemm2<<<N_PTS / 128, 256, 131072>>>(emb, W_dec);
    k_final<<<1, 32>>>(out, out_size);
}

// round 17
// speedup vs baseline: 3.2697x; 1.2127x over previous
#include <cuda_runtime.h>
#include <cuda_bf16.h>
#include <cstdint>

#define N_PTS 131072
#define D_IN  512
#define D_H   128
#define KC    256

typedef unsigned long long ull;

// ---------------- scratch (device globals; no allocation allowed) ----------
__device__ float  g_latentT[D_H * N_PTS];    // [d][m]
__device__ float  g_restoredT[D_H * N_PTS];  // [d][m]
__device__ float  g_cbnorm[3 * KC];
__device__ int    g_used[3 * KC];
__device__ double g_remsq;
__device__ double g_reconsq;

extern __shared__ char smem_raw[];

#define SMEM_SWIZZLE_128B(bo) ((bo) ^ (((bo) >> 3) & 0x70))

// ---------------- generic helpers ------------------------------------------
__device__ __forceinline__ uint32_t smem_to_u32(const void* p) {
    uint32_t a;
    asm("{ .reg .u64 t; cvta.to.shared.u64 t, %1; cvt.u32.u64 %0, t; }"
        : "=r"(a) : "l"(p));
    return a;
}
__device__ __forceinline__ float warp_sum(float v) {
    #pragma unroll
    for (int o = 16; o; o >>= 1) v += __shfl_xor_sync(0xffffffffu, v, o);
    return v;
}

// ---------------- mma.sync helpers (family-safe HMMA path) ------------------
__device__ __forceinline__ void ldmx4(uint32_t* r, uint32_t addr) {
    asm volatile("ldmatrix.sync.aligned.m8n8.x4.shared.b16 {%0,%1,%2,%3}, [%4];"
        : "=r"(r[0]), "=r"(r[1]), "=r"(r[2]), "=r"(r[3]) : "r"(addr));
}
__device__ __forceinline__ void mma16816(float* c, const uint32_t* a, const uint32_t* b) {
    asm volatile(
        "mma.sync.aligned.m16n8k16.row.col.f32.bf16.bf16.f32 "
        "{%0,%1,%2,%3}, {%4,%5,%6,%7}, {%8,%9}, {%0,%1,%2,%3};"
        : "+f"(c[0]), "+f"(c[1]), "+f"(c[2]), "+f"(c[3])
        : "r"(a[0]), "r"(a[1]), "r"(a[2]), "r"(a[3]), "r"(b[0]), "r"(b[1]));
}

// Convert one float4 (4 consecutive k of one row) into bf16 hi/lo tiles.
__device__ __forceinline__ void sts_split4(float4 v, int r, int kk, char* dh, char* dl) {
    uint32_t off = SMEM_SWIZZLE_128B((uint32_t)(r * 128 + kk * 2));
    __nv_bfloat162 h01 = __float22bfloat162_rn(make_float2(v.x, v.y));
    __nv_bfloat162 h23 = __float22bfloat162_rn(make_float2(v.z, v.w));
    float2 f01 = __bfloat1622float2(h01);
    float2 f23 = __bfloat1622float2(h23);
    __nv_bfloat162 l01 = __float22bfloat162_rn(make_float2(v.x - f01.x, v.y - f01.y));
    __nv_bfloat162 l23 = __float22bfloat162_rn(make_float2(v.z - f23.x, v.w - f23.y));
    uint2 hh, ll;
    hh.x = *reinterpret_cast<uint32_t*>(&h01);
    hh.y = *reinterpret_cast<uint32_t*>(&h23);
    ll.x = *reinterpret_cast<uint32_t*>(&l01);
    ll.y = *reinterpret_cast<uint32_t*>(&l23);
    *reinterpret_cast<uint2*>(dh + off) = hh;
    *reinterpret_cast<uint2*>(dl + off) = ll;
}

// Single-precision-level store: fp32x4 -> bf16x4 (hi only), swizzled.
__device__ __forceinline__ void sts_h4(float4 v, int r, int kk, char* dh) {
    uint32_t off = SMEM_SWIZZLE_128B((uint32_t)(r * 128 + kk * 2));
    __nv_bfloat162 h01 = __float22bfloat162_rn(make_float2(v.x, v.y));
    __nv_bfloat162 h23 = __float22bfloat162_rn(make_float2(v.z, v.w));
    uint2 hh;
    hh.x = *reinterpret_cast<uint32_t*>(&h01);
    hh.y = *reinterpret_cast<uint32_t*>(&h23);
    *reinterpret_cast<uint2*>(dh + off) = hh;
}

// Stage A[m][k] 128x64 from K-major source srcT[k][m] into bf16 hi/lo tiles.
__device__ __forceinline__ void stage_colmajor_split(
    const float* __restrict__ srcT, int m0, int k0,
    char* dh, char* dl, int tid)
{
    int kr = tid & 63, mq = tid >> 6;
    const float4* p = reinterpret_cast<const float4*>(
        srcT + (size_t)(k0 + kr) * N_PTS + m0 + mq * 32);
    #pragma unroll
    for (int q = 0; q < 8; q++) {
        float4 v = p[q];
        int mb = mq * 32 + q * 4;
        float vv[4] = {v.x, v.y, v.z, v.w};
        #pragma unroll
        for (int e = 0; e < 4; e++) {
            float a = vv[e];
            __nv_bfloat16 h = __float2bfloat16(a);
            __nv_bfloat16 l = __float2bfloat16(a - __bfloat162float(h));
            uint32_t off = SMEM_SWIZZLE_128B((uint32_t)((mb + e) * 128 + kr * 2));
            *reinterpret_cast<__nv_bfloat16*>(dh + off) = h;
            *reinterpret_cast<__nv_bfloat16*>(dl + off) = l;
        }
    }
}

// 3-combo K=64 chunk (used by k_gemm1). Warp tile 32m x 64n.
__device__ __forceinline__ void mma_chunk2(
    float acc[2][8][4], char* Ah, char* Al, char* Bh, char* Bl,
    int wm, int wn, int lane)
{
    uint32_t ahB = smem_to_u32(Ah), alB = smem_to_u32(Al);
    uint32_t bhB = smem_to_u32(Bh), blB = smem_to_u32(Bl);
    const int g = lane >> 3, rr = lane & 7;
    const int a_row = (g & 1) * 8 + rr, a_col = (g >> 1) * 8;
    const int b_row = (g >> 1) * 8 + rr, b_col = (g & 1) * 8;
    #pragma unroll
    for (int ks = 0; ks < 4; ks++) {
        const int k0 = ks * 16;
        uint32_t ah[2][4], al[2][4];
        #pragma unroll
        for (int mt = 0; mt < 2; mt++) {
            uint32_t off = SMEM_SWIZZLE_128B(
                (uint32_t)((wm + mt * 16 + a_row) * 128 + (k0 + a_col) * 2));
            ldmx4(ah[mt], ahB + off);
            ldmx4(al[mt], alB + off);
        }
        #pragma unroll
        for (int np = 0; np < 4; np++) {
            uint32_t bh[4], bl[4];
            uint32_t off = SMEM_SWIZZLE_128B(
                (uint32_t)((wn + np * 16 + b_row) * 128 + (k0 + b_col) * 2));
            ldmx4(bh, bhB + off);
            ldmx4(bl, blB + off);
            #pragma unroll
            for (int mt = 0; mt < 2; mt++)
                #pragma unroll
                for (int h = 0; h < 2; h++) {
                    float* c = acc[mt][np * 2 + h];
                    mma16816(c, ah[mt], bh + h * 2);
                    mma16816(c, al[mt], bh + h * 2);
                    mma16816(c, ah[mt], bl + h * 2);
                }
        }
    }
}

// 2-combo K=64 chunk (A split, B single bf16). Used by k_gemm2.
__device__ __forceinline__ void mma_chunk_2c(
    float acc[2][8][4], char* Ah, char* Al, char* Bh,
    int wm, int wn, int lane)
{
    uint32_t ahB = smem_to_u32(Ah), alB = smem_to_u32(Al);
    uint32_t bhB = smem_to_u32(Bh);
    const int g = lane >> 3, rr = lane & 7;
    const int a_row = (g & 1) * 8 + rr, a_col = (g >> 1) * 8;
    const int b_row = (g >> 1) * 8 + rr, b_col = (g & 1) * 8;
    #pragma unroll
    for (int ks = 0; ks < 4; ks++) {
        const int k0 = ks * 16;
        uint32_t ah[2][4], al[2][4];
        #pragma unroll
        for (int mt = 0; mt < 2; mt++) {
            uint32_t off = SMEM_SWIZZLE_128B(
                (uint32_t)((wm + mt * 16 + a_row) * 128 + (k0 + a_col) * 2));
            ldmx4(ah[mt], ahB + off);
            ldmx4(al[mt], alB + off);
        }
        #pragma unroll
        for (int np = 0; np < 4; np++) {
            uint32_t bh[4];
            uint32_t off = SMEM_SWIZZLE_128B(
                (uint32_t)((wn + np * 16 + b_row) * 128 + (k0 + b_col) * 2));
            ldmx4(bh, bhB + off);
            #pragma unroll
            for (int mt = 0; mt < 2; mt++)
                #pragma unroll
                for (int h = 0; h < 2; h++) {
                    float* c = acc[mt][np * 2 + h];
                    mma16816(c, ah[mt], bh + h * 2);
                    mma16816(c, al[mt], bh + h * 2);
                }
        }
    }
}

// ---------------- K0: init + codebook norms --------------------------------
__global__ void k_init(const float* __restrict__ cb0,
                       const float* __restrict__ cb1,
                       const float* __restrict__ cb2) {
    int i = blockIdx.x * 256 + threadIdx.x;
    if (i == 0) { g_remsq = 0.0; g_reconsq = 0.0; }
    if (i < 3 * KC) {
        g_used[i] = 0;
        const float* cb = (i < KC) ? cb0 : (i < 2 * KC ? cb1 : cb2);
        int c = i & (KC - 1);
        float s = 0.f;
        #pragma unroll 8
        for (int d = 0; d < D_H; d++) { float v = cb[c * D_H + d]; s = fmaf(v, v, s); }
        g_cbnorm[i] = s;
    }
}

// ---------------- GEMM1 (HMMA bf16x3): latentT = (emb @ W_enc^T)^T ---------
__global__ void __launch_bounds__(256, 1)
k_gemm1(const float* __restrict__ emb, const float* __restrict__ W_enc) {
    char* Ah = smem_raw;
    char* Al = smem_raw + 16384;
    char* Bh = smem_raw + 32768;
    char* Bl = smem_raw + 49152;
    const int tid = threadIdx.x, lane = tid & 31, wid = tid >> 5;
    const int m0 = blockIdx.x * 128;
    const int wm = (wid >> 1) * 32, wn = (wid & 1) * 64;
    const int r = tid >> 1, half = tid & 1;

    float acc[2][8][4];
    #pragma unroll
    for (int i = 0; i < 2; i++)
        #pragma unroll
        for (int j = 0; j < 8; j++)
            #pragma unroll
            for (int k = 0; k < 4; k++) acc[i][j][k] = 0.f;

    const float* aRow = emb + (size_t)(m0 + r) * 512 + half * 32;
    const float* bRow = W_enc + (size_t)r * 512 + half * 32;

    float4 pa[8];
    #pragma unroll
    for (int q = 0; q < 8; q++) pa[q] = reinterpret_cast<const float4*>(aRow)[q];

    for (int ch = 0; ch < 8; ch++) {
        #pragma unroll
        for (int q = 0; q < 8; q++) {
            sts_split4(pa[q], r, half * 32 + q * 4, Ah, Al);
            float4 vb = reinterpret_cast<const float4*>(bRow + ch * 64)[q];
            sts_split4(vb, r, half * 32 + q * 4, Bh, Bl);
        }
        __syncthreads();
        if (ch < 7) {
            #pragma unroll
            for (int q = 0; q < 8; q++)
                pa[q] = reinterpret_cast<const float4*>(aRow + (ch + 1) * 64)[q];
        }
        mma_chunk2(acc, Ah, Al, Bh, Bl, wm, wn, lane);
        __syncthreads();
    }

    #pragma unroll
    for (int mt = 0; mt < 2; mt++) {
        int m = m0 + wm + mt * 16 + (lane >> 2);
        #pragma unroll
        for (int nt = 0; nt < 8; nt++) {
            int n = wn + nt * 8 + (lane & 3) * 2;
            g_latentT[(size_t)n * N_PTS + m]           = acc[mt][nt][0];
            g_latentT[(size_t)(n + 1) * N_PTS + m]     = acc[mt][nt][1];
            g_latentT[(size_t)n * N_PTS + m + 8]       = acc[mt][nt][2];
            g_latentT[(size_t)(n + 1) * N_PTS + m + 8] = acc[mt][nt][3];
        }
    }
}

// ---------------- K2: fused 3-stage RQ, single-bf16 distance GEMM ----------
// Argmin only needs ranking; remainder update stays exact fp32, so the
// bf16 quantization can only flip genuinely-ambiguous boundary points.
struct SmemStg3 {
    float remF[128][132];       // fp32 remainder (67.6 KB)
    char  Ah0[16384];           // rem bf16, k 0..63
    char  Ah1[16384];           // rem bf16, k 64..127
    char  Bh0[32768];           // codebook bf16, k 0..63   (256 rows)
    char  Bh1[32768];           // codebook bf16, k 64..127
    float cbn[KC];
    float bestS[2][128];
    int   bestI[2][128];
};

__global__ void __launch_bounds__(256, 1)
k_stages(const float* __restrict__ cb0, const float* __restrict__ cb1,
         const float* __restrict__ cb2g) {
    SmemStg3& S = *reinterpret_cast<SmemStg3*>(smem_raw);
    const int tid = threadIdx.x, lane = tid & 31, wid = tid >> 5;
    const int m0 = blockIdx.x * 128;
    const int wm = (wid >> 1) * 32;        // 4 m-groups of 32
    const int wn = (wid & 1) * 128;        // 2 n-groups of 128

    for (int idx = tid; idx < 128 * 128; idx += 256) {
        int m = idx & 127, k = idx >> 7;
        S.remF[m][k] = g_latentT[(size_t)k * N_PTS + m0 + m];
    }

    float sq = 0.f;
    for (int s = 0; s < 3; s++) {
        const float* cb = (s == 0) ? cb0 : (s == 1 ? cb1 : cb2g);
        __syncthreads();   // remF updates from prev stage / tile readers done
        S.cbn[tid] = g_cbnorm[s * KC + tid];

        // stage A (rem -> bf16), both chunks: 128 rows x 32 float4
        #pragma unroll
        for (int i = 0; i < 16; i++) {
            int idx = tid + i * 256;
            int r = idx >> 5, q = idx & 31;
            int ch = q >> 4, f4 = q & 15;
            float4 v = *reinterpret_cast<const float4*>(&S.remF[r][ch * 64 + f4 * 4]);
            sts_h4(v, r, f4 * 4, ch ? S.Ah1 : S.Ah0);
        }
        // stage B (codebook -> bf16), both chunks: 256 rows x 32 float4
        #pragma unroll
        for (int i = 0; i < 32; i++) {
            int idx = tid + i * 256;
            int n = idx >> 5, q = idx & 31;
            int ch = q >> 4, f4 = q & 15;
            float4 v = *reinterpret_cast<const float4*>(
                cb + (size_t)n * 128 + ch * 64 + f4 * 4);
            sts_h4(v, n, f4 * 4, ch ? S.Bh1 : S.Bh0);
        }
        __syncthreads();

        float acc[2][16][4];
        #pragma unroll
        for (int i = 0; i < 2; i++)
            #pragma unroll
            for (int j = 0; j < 16; j++)
                #pragma unroll
                for (int k = 0; k < 4; k++) acc[i][j][k] = 0.f;

        const int g = lane >> 3, rr = lane & 7;
        const int a_row = (g & 1) * 8 + rr, a_col = (g >> 1) * 8;
        const int b_row = (g >> 1) * 8 + rr, b_col = (g & 1) * 8;
        #pragma unroll
        for (int ch = 0; ch < 2; ch++) {
            uint32_t aB = smem_to_u32(ch ? S.Ah1 : S.Ah0);
            uint32_t bB = smem_to_u32(ch ? S.Bh1 : S.Bh0);
            #pragma unroll
            for (int ks = 0; ks < 4; ks++) {
                const int k0 = ks * 16;
                uint32_t a[2][4];
                #pragma unroll
                for (int mt = 0; mt < 2; mt++)
                    ldmx4(a[mt], aB + SMEM_SWIZZLE_128B(
                        (uint32_t)((wm + mt * 16 + a_row) * 128 + (k0 + a_col) * 2)));
                #pragma unroll
                for (int np = 0; np < 8; np++) {
                    uint32_t b[4];
                    ldmx4(b, bB + SMEM_SWIZZLE_128B(
                        (uint32_t)((wn + np * 16 + b_row) * 128 + (k0 + b_col) * 2)));
                    #pragma unroll
                    for (int mt = 0; mt < 2; mt++)
                        #pragma unroll
                        for (int h = 0; h < 2; h++)
                            mma16816(acc[mt][np * 2 + h], a[mt], b + h * 2);
                }
            }
        }

        // ---- argmin: score = cbn[n] - 2*dot ----
        float bs[2][2]; int bn[2][2];
        #pragma unroll
        for (int mt = 0; mt < 2; mt++)
            #pragma unroll
            for (int rh = 0; rh < 2; rh++) { bs[mt][rh] = 3.4e38f; bn[mt][rh] = 0; }
        #pragma unroll
        for (int nt = 0; nt < 16; nt++) {
            #pragma unroll
            for (int mt = 0; mt < 2; mt++)
                #pragma unroll
                for (int rh = 0; rh < 2; rh++)
                    #pragma unroll
                    for (int e = 0; e < 2; e++) {
                        int n = wn + nt * 8 + (lane & 3) * 2 + e;
                        float sc = S.cbn[n] - 2.f * acc[mt][nt][rh * 2 + e];
                        if (sc < bs[mt][rh] ||
                            (sc == bs[mt][rh] && n < bn[mt][rh])) {
                            bs[mt][rh] = sc; bn[mt][rh] = n;
                        }
                    }
        }
        #pragma unroll
        for (int o = 1; o < 4; o <<= 1) {
            #pragma unroll
            for (int mt = 0; mt < 2; mt++)
                #pragma unroll
                for (int rh = 0; rh < 2; rh++) {
                    float so = __shfl_xor_sync(0xffffffffu, bs[mt][rh], o);
                    int   no = __shfl_xor_sync(0xffffffffu, bn[mt][rh], o);
                    if (so < bs[mt][rh] ||
                        (so == bs[mt][rh] && no < bn[mt][rh])) {
                        bs[mt][rh] = so; bn[mt][rh] = no;
                    }
                }
        }
        if ((lane & 3) == 0) {
            #pragma unroll
            for (int mt = 0; mt < 2; mt++)
                #pragma unroll
                for (int rh = 0; rh < 2; rh++) {
                    int ml = wm + mt * 16 + (lane >> 2) + rh * 8;
                    S.bestS[wid & 1][ml] = bs[mt][rh];
                    S.bestI[wid & 1][ml] = bn[mt][rh];
                }
        }
        __syncthreads();

        // ---- exact fp32 remainder update + loss accumulation ----
        {
            int m = tid >> 1, kh = tid & 1;
            float s0 = S.bestS[0][m], s1 = S.bestS[1][m];
            int bi = (s1 < s0) ? S.bestI[1][m] : S.bestI[0][m];
            if (kh == 0) g_used[s * KC + bi] = 1;
            const float4* crow = reinterpret_cast<const float4*>(
                cb + (size_t)bi * 128 + kh * 64);
            float4* rrow = reinterpret_cast<float4*>(&S.remF[m][kh * 64]);
            #pragma unroll
            for (int q = 0; q < 16; q++) {
                float4 cv = crow[q];
                float4 rv = rrow[q];
                rv.x -= cv.x; rv.y -= cv.y; rv.z -= cv.z; rv.w -= cv.w;
                sq = fmaf(rv.x, rv.x, sq); sq = fmaf(rv.y, rv.y, sq);
                sq = fmaf(rv.z, rv.z, sq); sq = fmaf(rv.w, rv.w, sq);
                rrow[q] = rv;
            }
        }
    }
    __syncthreads();

    for (int idx = tid; idx < 128 * 128; idx += 256) {
        int m = idx & 127, k = idx >> 7;
        g_restoredT[(size_t)k * N_PTS + m0 + m] =
            g_latentT[(size_t)k * N_PTS + m0 + m] - S.remF[m][k];
    }
    float tot = warp_sum(sq);
    if (lane == 0) atomicAdd(&g_remsq, (double)tot);
}

// ---------------- GEMM2 (HMMA bf16, A split x B single) + fused MSE --------
// One CTA per 128-m tile; loops all 4 n-tiles with A staged once.
__global__ void __launch_bounds__(256, 1)
k_gemm2(const float* __restrict__ emb, const float* __restrict__ W_dec) {
    char* A0h = smem_raw;
    char* A0l = smem_raw + 16384;
    char* A1h = smem_raw + 32768;
    char* A1l = smem_raw + 49152;
    char* B0h = smem_raw + 65536;
    char* B1h = smem_raw + 81920;
    const int tid = threadIdx.x, lane = tid & 31, wid = tid >> 5;
    const int m0 = blockIdx.x * 128;
    const int wm = (wid >> 1) * 32, wn = (wid & 1) * 64;
    const int r = tid >> 1, half = tid & 1;

    stage_colmajor_split(g_restoredT, m0, 0,  A0h, A0l, tid);
    stage_colmajor_split(g_restoredT, m0, 64, A1h, A1l, tid);

    float sq = 0.f;
    for (int nt = 0; nt < 4; nt++) {
        const int n0 = nt * 128;
        __syncthreads();  // A visible (nt=0) / previous-nt B readers done
        #pragma unroll
        for (int q = 0; q < 8; q++) {
            float4 v0 = reinterpret_cast<const float4*>(
                W_dec + (size_t)(n0 + r) * 128 + half * 32)[q];
            sts_h4(v0, r, half * 32 + q * 4, B0h);
            float4 v1 = reinterpret_cast<const float4*>(
                W_dec + (size_t)(n0 + r) * 128 + 64 + half * 32)[q];
            sts_h4(v1, r, half * 32 + q * 4, B1h);
        }
        __syncthreads();

        float acc[2][8][4];
        #pragma unroll
        for (int i = 0; i < 2; i++)
            #pragma unroll
            for (int j = 0; j < 8; j++)
                #pragma unroll
                for (int k = 0; k < 4; k++) acc[i][j][k] = 0.f;

        mma_chunk_2c(acc, A0h, A0l, B0h, wm, wn, lane);
        mma_chunk_2c(acc, A1h, A1l, B1h, wm, wn, lane);

        // fused MSE epilogue for this n-tile
        #pragma unroll
        for (int mt = 0; mt < 2; mt++) {
            int m = m0 + wm + mt * 16 + (lane >> 2);
            #pragma unroll
            for (int ntile = 0; ntile < 8; ntile++) {
                int n = n0 + wn + ntile * 8 + (lane & 3) * 2;
                float2 e0 = *reinterpret_cast<const float2*>(emb + (size_t)m * 512 + n);
                float2 e1 = *reinterpret_cast<const float2*>(emb + (size_t)(m + 8) * 512 + n);
                float d0 = acc[mt][ntile][0] - e0.x;
                float d1 = acc[mt][ntile][1] - e0.y;
                float d2 = acc[mt][ntile][2] - e1.x;
                float d3 = acc[mt][ntile][3] - e1.y;
                sq = fmaf(d0, d0, sq); sq = fmaf(d1, d1, sq);
                sq = fmaf(d2, d2, sq); sq = fmaf(d3, d3, sq);
            }
        }
    }
    float tot = warp_sum(sq);
    if (lane == 0) atomicAdd(&g_reconsq, (double)tot);
}

// ---------------- K4: finalize ---------------------------------------------
__global__ void k_final(float* __restrict__ out, int out_size) {
    __shared__ float vals[6];
    int tid = threadIdx.x;
    if (tid == 0) {
        double recon = g_reconsq / ((double)N_PTS * (double)D_IN);
        double rq    = 1.25 * g_remsq / ((double)N_PTS * (double)D_H);
        vals[0] = (float)(recon + rq);
        vals[1] = (float)recon;
        vals[2] = (float)rq;
    }
    if (tid < 3) {
        int cnt = 0;
        for (int c = 0; c < KC; c++) cnt += g_used[tid * KC + c];
        vals[3 + tid] = (float)cnt;
    }
    __syncthreads();
    if (tid < 6 && tid < out_size) out[tid] = vals[tid];
}

// ---------------- launch ----------------------------------------------------
extern "C" void kernel_launch(void* const* d_in, const int* in_sizes, int n_in,
                              void* d_out, int out_size) {
    const float* emb   = (const float*)d_in[0];
    const float* W_enc = (const float*)d_in[1];
    const float* W_dec = (const float*)d_in[2];
    const float* cb0   = (const float*)d_in[3];
    const float* cb1   = (const float*)d_in[4];
    const float* cb2   = (const float*)d_in[5];
    float* out = (float*)d_out;

    cudaFuncSetAttribute(k_gemm1, cudaFuncAttributeMaxDynamicSharedMemorySize, 65536);
    cudaFuncSetAttribute(k_gemm2, cudaFuncAttributeMaxDynamicSharedMemorySize, 98304);
    cudaFuncSetAttribute(k_stages, cudaFuncAttributeMaxDynamicSharedMemorySize,
                         (int)sizeof(SmemStg3));

    k_init<<<3, 256>>>(cb0, cb1, cb2);
    k_gemm1<<<N_PTS / 128, 256, 65536>>>(emb, W_enc);
    k_stages<<<N_PTS / 128, 256, sizeof(SmemStg3)>>>(cb0, cb1, cb2);
    k_gemm2<<<N_PTS / 128, 256, 98304>>>(emb, W_dec);
    k_final<<<1, 32>>>(out, out_size);
}